// round 3
// baseline (speedup 1.0000x reference)
#include <cuda_runtime.h>

// Problem constants (fixed shapes)
constexpr int DIN      = 1024;   // input dim
constexpr int L        = 65;     // NUM_FREQ + 1
constexpr int N1       = 130;    // 2L (GEMM1 output cols)
constexpr int F        = 64;     // NUM_FREQ
constexpr int K2       = 128;    // 2F (GEMM2 reduction)
constexpr int D        = 512;    // DIM_OUTPUT
constexpr int ROWS_MAX = 65536;  // 16 * 4096

// Scratch (static device globals — no runtime allocation)
__device__ float g_p[(size_t)ROWS_MAX * N1];      // GEMM1 output
__device__ float g_coef[(size_t)ROWS_MAX * K2];   // [c.re | c.im]
__device__ float g_T[(size_t)K2 * D];             // rows 0..63: cos, 64..127: -sin
__device__ float g_CS[F];                         // sum_d cos(phase[d,f])
__device__ float g_SS[F];                         // sum_d sin(phase[d,f])
__device__ float g_invS[ROWS_MAX];                // 1 / row-sum of like

// ---- packed f32x2 helpers (sm_100+) ----
__device__ __forceinline__ void fma2(unsigned long long& d, unsigned long long a,
                                     unsigned long long b) {
    asm("fma.rn.f32x2 %0, %1, %2, %0;" : "+l"(d) : "l"(a), "l"(b));
}
__device__ __forceinline__ unsigned long long dup2(float w) {
    unsigned long long r;
    asm("mov.b64 %0, {%1, %1};" : "=l"(r) : "f"(w));
    return r;
}
__device__ __forceinline__ float lo32(unsigned long long v) {
    return __uint_as_float((unsigned)(v & 0xffffffffu));
}
__device__ __forceinline__ float hi32(unsigned long long v) {
    return __uint_as_float((unsigned)(v >> 32));
}

// ============================================================
// Kernel 0: build cos/sin table + column sums
// grid (64), block (512): f = blockIdx.x, d = threadIdx.x
// ============================================================
__global__ void table_kernel() {
    const int f = blockIdx.x;
    const int d = threadIdx.x;
    // centers on [-1, 1]: center[d] = -1 + (2d+1)/512
    float center = -1.0f + (2 * d + 1) * (1.0f / 512.0f);
    float arg = center * (float)(f + 1);     // phase / pi
    float s, c;
    sincospif(arg, &s, &c);
    g_T[(size_t)f * D + d] = c;
    g_T[(size_t)(F + f) * D + d] = -s;

    __shared__ float sc[512], ss[512];
    sc[d] = c;
    ss[d] = s;
    __syncthreads();
    for (int off = 256; off > 0; off >>= 1) {
        if (d < off) {
            sc[d] += sc[d + off];
            ss[d] += ss[d + off];
        }
        __syncthreads();
    }
    if (d == 0) {
        g_CS[f] = sc[0];
        g_SS[f] = ss[0];
    }
}

// ============================================================
// Kernel 1: p = X @ W^T + b
// M=rows, N=130 (padded 160), K=1024
// BM=128, BN=160, BK=16, 256 threads, microtile 8 rows x 10 cols
// (rows packed in pairs for f32x2)
// ============================================================
#define BM1 128
#define BN1 160
#define BK1 16

__global__ void __launch_bounds__(256)
gemm1_kernel(const float* __restrict__ X, const float* __restrict__ Wm,
             const float* __restrict__ bias) {
    __shared__ float xs[BK1][BM1];
    __shared__ float ws[BK1][BN1];
    const int tid = threadIdx.x;
    const int tx = tid & 15;   // col group (10 cols each)
    const int ty = tid >> 4;   // row group (8 rows each)
    const int m0 = blockIdx.x * BM1;

    unsigned long long acc[4][10];
#pragma unroll
    for (int i = 0; i < 4; i++)
#pragma unroll
        for (int j = 0; j < 10; j++) acc[i][j] = 0ULL;

    for (int kk = 0; kk < DIN; kk += BK1) {
        // X tile: 128 rows x 16 k, float4 loads, transpose into xs[k][row]
#pragma unroll
        for (int it = 0; it < 2; it++) {
            int idx = tid + 256 * it;   // 0..511
            int row = idx >> 2;
            int k4 = idx & 3;
            float4 v = *(const float4*)(X + (size_t)(m0 + row) * DIN + kk + k4 * 4);
            xs[k4 * 4 + 0][row] = v.x;
            xs[k4 * 4 + 1][row] = v.y;
            xs[k4 * 4 + 2][row] = v.z;
            xs[k4 * 4 + 3][row] = v.w;
        }
        // W tile: 160 cols x 16 k (cols >= 130 are zero)
#pragma unroll
        for (int it = 0; it < 10; it++) {
            int t = tid + 256 * it;     // < 2560
            int k = t & 15;
            int n = t >> 4;
            ws[k][n] = (n < N1) ? Wm[(size_t)n * DIN + kk + k] : 0.0f;
        }
        __syncthreads();
#pragma unroll
        for (int k = 0; k < BK1; k++) {
            unsigned long long xv[4];
#pragma unroll
            for (int i = 0; i < 4; i++)
                xv[i] = *(const unsigned long long*)&xs[k][ty * 8 + 2 * i];
#pragma unroll
            for (int j = 0; j < 10; j++) {
                unsigned long long wd = dup2(ws[k][tx * 10 + j]);
#pragma unroll
                for (int i = 0; i < 4; i++) fma2(acc[i][j], xv[i], wd);
            }
        }
        __syncthreads();
    }
#pragma unroll
    for (int j = 0; j < 10; j++) {
        int col = tx * 10 + j;
        if (col < N1) {
            float bv = __ldg(bias + col);
#pragma unroll
            for (int i = 0; i < 4; i++) {
                int r = m0 + ty * 8 + 2 * i;
                g_p[(size_t)r * N1 + col] = lo32(acc[i][j]) + bv;
                g_p[(size_t)(r + 1) * N1 + col] = hi32(acc[i][j]) + bv;
            }
        }
    }
}

// ============================================================
// Kernel 2: per-row complex autocorrelation + normalization coeffs
// r[k] = sum_j a[j+k] * conj(a[j]);  c = r[1:]/r[0].re
// also invS = 1 / (256 + sum_f cr*CS - ci*SS)
// grid (rows), block (128)
// ============================================================
__global__ void __launch_bounds__(128) autocorr_kernel() {
    const int row = blockIdx.x;
    __shared__ float px[L], py[L];
    __shared__ float rr[L], ri[L];
    __shared__ float partS[L];
    const int t = threadIdx.x;
    // N1 = 130 > blockDim = 128: strided loop so ALL elements are loaded
    for (int idx = t; idx < N1; idx += 128) {
        float v = g_p[(size_t)row * N1 + idx];
        if (idx < L) px[idx] = v;
        else py[idx - L] = v;
    }
    __syncthreads();
    if (t < L) {
        float sre = 0.0f, sim = 0.0f;
        for (int j = 0; j + t < L; j++) {
            float xj = px[j], yj = py[j];
            float xk = px[j + t], yk = py[j + t];
            sre += xk * xj + yk * yj;
            sim += yk * xj - xk * yj;
        }
        rr[t] = sre;
        ri[t] = sim;
    }
    __syncthreads();
    if (t >= 1 && t < L) {
        float cr = rr[t] / rr[0];
        float ci = ri[t] / rr[0];
        g_coef[(size_t)row * K2 + (t - 1)] = cr;
        g_coef[(size_t)row * K2 + F + (t - 1)] = ci;
        partS[t] = cr * g_CS[t - 1] - ci * g_SS[t - 1];
    }
    __syncthreads();
    if (t == 0) {
        float S = 0.5f * (float)D;   // sum of the 0.5 offsets over 512 bins
        for (int k = 1; k < L; k++) S += partS[k];
        g_invS[row] = 1.0f / S;
    }
}

// ============================================================
// Kernel 3: like = coef @ T  (+0.5), fused normalize + log epilogue
// M=rows, N=512, K=128. BM=128, BN=128, BK=16, 256 threads, 8x8 microtile
// ============================================================
#define BM2 128
#define BN2 128
#define BK2 16

__global__ void __launch_bounds__(256) gemm2_kernel(float* __restrict__ out) {
    __shared__ float as_[BK2][BM2];
    __shared__ float bs[BK2][BN2];
    const int tid = threadIdx.x;
    const int tx = tid & 15;
    const int ty = tid >> 4;
    const int m0 = blockIdx.x * BM2;
    const int n0 = blockIdx.y * BN2;

    unsigned long long acc[4][8];
#pragma unroll
    for (int i = 0; i < 4; i++)
#pragma unroll
        for (int j = 0; j < 8; j++) acc[i][j] = 0ULL;

    for (int kk = 0; kk < K2; kk += BK2) {
        // A tile (coef): 128 rows x 16 k
#pragma unroll
        for (int it = 0; it < 2; it++) {
            int idx = tid + 256 * it;
            int row = idx >> 2;
            int k4 = idx & 3;
            float4 v = *(const float4*)(g_coef + (size_t)(m0 + row) * K2 + kk + k4 * 4);
            as_[k4 * 4 + 0][row] = v.x;
            as_[k4 * 4 + 1][row] = v.y;
            as_[k4 * 4 + 2][row] = v.z;
            as_[k4 * 4 + 3][row] = v.w;
        }
        // B tile (table): 16 k x 128 n
#pragma unroll
        for (int it = 0; it < 8; it++) {
            int t = tid + 256 * it;     // < 2048
            int k = t >> 7;
            int n = t & 127;
            bs[k][n] = g_T[(size_t)(kk + k) * D + n0 + n];
        }
        __syncthreads();
#pragma unroll
        for (int k = 0; k < BK2; k++) {
            unsigned long long av[4];
#pragma unroll
            for (int i = 0; i < 4; i++)
                av[i] = *(const unsigned long long*)&as_[k][ty * 8 + 2 * i];
#pragma unroll
            for (int j = 0; j < 8; j++) {
                unsigned long long wd = dup2(bs[k][tx * 8 + j]);
#pragma unroll
                for (int i = 0; i < 4; i++) fma2(acc[i][j], av[i], wd);
            }
        }
        __syncthreads();
    }
    // Epilogue: logits = log((0.5 + acc) * invS + 1e-5)
#pragma unroll
    for (int i = 0; i < 4; i++) {
        int r = m0 + ty * 8 + 2 * i;
        float is0 = g_invS[r];
        float is1 = g_invS[r + 1];
        float o0[8], o1[8];
#pragma unroll
        for (int j = 0; j < 8; j++) {
            o0[j] = logf(fmaf(lo32(acc[i][j]) + 0.5f, is0, 1e-5f));
            o1[j] = logf(fmaf(hi32(acc[i][j]) + 0.5f, is1, 1e-5f));
        }
        float* p0 = out + (size_t)r * D + n0 + tx * 8;
        *(float4*)(p0 + 0) = make_float4(o0[0], o0[1], o0[2], o0[3]);
        *(float4*)(p0 + 4) = make_float4(o0[4], o0[5], o0[6], o0[7]);
        float* p1 = out + (size_t)(r + 1) * D + n0 + tx * 8;
        *(float4*)(p1 + 0) = make_float4(o1[0], o1[1], o1[2], o1[3]);
        *(float4*)(p1 + 4) = make_float4(o1[4], o1[5], o1[6], o1[7]);
    }
}

extern "C" void kernel_launch(void* const* d_in, const int* in_sizes, int n_in,
                              void* d_out, int out_size) {
    const float* X = (const float*)d_in[0];     // batch [16,4096,1024]
    const float* Wm = (const float*)d_in[1];    // W [130,1024]
    const float* bias = (const float*)d_in[2];  // b [130]
    float* out = (float*)d_out;                 // [16,4096,512] f32

    const int rows = in_sizes[0] / DIN;         // 65536

    table_kernel<<<F, D>>>();
    gemm1_kernel<<<rows / BM1, 256>>>(X, Wm, bias);
    autocorr_kernel<<<rows, 128>>>();
    gemm2_kernel<<<dim3(rows / BM2, D / BN2), 256>>>(out);
}

// round 4
// speedup vs baseline: 1.0157x; 1.0157x over previous
#include <cuda_runtime.h>

// Problem constants (fixed shapes)
constexpr int DIN      = 1024;   // input dim
constexpr int L        = 65;     // NUM_FREQ + 1
constexpr int N1       = 130;    // 2L (GEMM1 output cols)
constexpr int F        = 64;     // NUM_FREQ
constexpr int K2       = 128;    // 2F (GEMM2 reduction)
constexpr int D        = 512;    // DIM_OUTPUT
constexpr int ROWS_MAX = 65536;  // 16 * 4096

// Scratch (static device globals — no runtime allocation)
__device__ float g_coef[(size_t)ROWS_MAX * K2];   // [c.re | c.im]
__device__ float g_T[(size_t)K2 * D];             // rows 0..63: cos, 64..127: -sin
__device__ float g_CS[F];                         // sum_d cos(phase[d,f])
__device__ float g_SS[F];                         // sum_d sin(phase[d,f])
__device__ float g_invS[ROWS_MAX];                // 1 / row-sum of like

// ---- packed f32x2 helpers (sm_100+) ----
__device__ __forceinline__ void fma2(unsigned long long& d, unsigned long long a,
                                     unsigned long long b) {
    asm("fma.rn.f32x2 %0, %1, %2, %0;" : "+l"(d) : "l"(a), "l"(b));
}
__device__ __forceinline__ unsigned long long dup2(float w) {
    unsigned long long r;
    asm("mov.b64 %0, {%1, %1};" : "=l"(r) : "f"(w));
    return r;
}
__device__ __forceinline__ float lo32(unsigned long long v) {
    return __uint_as_float((unsigned)(v & 0xffffffffu));
}
__device__ __forceinline__ float hi32(unsigned long long v) {
    return __uint_as_float((unsigned)(v >> 32));
}

// ============================================================
// Kernel 0: build cos/sin table + column sums
// ============================================================
__global__ void table_kernel() {
    const int f = blockIdx.x;
    const int d = threadIdx.x;
    float center = -1.0f + (2 * d + 1) * (1.0f / 512.0f);
    float arg = center * (float)(f + 1);     // phase / pi
    float s, c;
    sincospif(arg, &s, &c);
    g_T[(size_t)f * D + d] = c;
    g_T[(size_t)(F + f) * D + d] = -s;

    __shared__ float sc[512], ss[512];
    sc[d] = c;
    ss[d] = s;
    __syncthreads();
    for (int off = 256; off > 0; off >>= 1) {
        if (d < off) {
            sc[d] += sc[d + off];
            ss[d] += ss[d + off];
        }
        __syncthreads();
    }
    if (d == 0) {
        g_CS[f] = sc[0];
        g_SS[f] = ss[0];
    }
}

// ============================================================
// Kernel 1 (FUSED): p = X @ W^T + b  ->  autocorr -> coef + invS
// M=rows, N=130 (padded 160), K=1024
// BM=128, BN=160, BK=16, 256 threads, microtile 8 rows x 10 cols
// Double-buffered smem, register prefetch.
// Epilogue: block-local complex autocorrelation (all 130 cols are
// resident in this block), writes g_coef and g_invS directly.
// ============================================================
#define BM1 128
#define BN1 160
#define BK1 16

// dynamic smem layout:
//  mainloop (aliased):  xs[2][16][128]  ws[2][16][160]   (36,864 B)
//  epilogue (aliased):  px[128][65] py[128][65] contrib[128][64] inv_r0[128]
constexpr int SM1_FLOATS = 128 * 65 * 2 + 128 * 64 + 128;   // 24,960
constexpr int SM1_BYTES  = SM1_FLOATS * 4;                  // 99,840

__global__ void __launch_bounds__(256)
gemm1_fused_kernel(const float* __restrict__ X, const float* __restrict__ Wm,
                   const float* __restrict__ bias) {
    extern __shared__ float sm[];
    float* xs = sm;                    // [2][16][128]
    float* ws = sm + 2 * BK1 * BM1;    // [2][16][160]
    const int tid = threadIdx.x;
    const int tx = tid & 15;   // col group (10 cols each)
    const int ty = tid >> 4;   // row group (8 rows each)
    const int m0 = blockIdx.x * BM1;

    unsigned long long acc[4][10];
#pragma unroll
    for (int i = 0; i < 4; i++)
#pragma unroll
        for (int j = 0; j < 10; j++) acc[i][j] = 0ULL;

    // load addresses
    const int xrow = tid >> 2;         // 0..63 (+64 for it=1)
    const int xk4  = tid & 3;
    const int wk   = tid & 15;
    const int wn   = tid >> 4;         // 0..15 (+16*it)

    // ---- preload tile 0 into buffer 0 ----
    {
#pragma unroll
        for (int it = 0; it < 2; it++) {
            int row = xrow + 64 * it;
            float4 v = *(const float4*)(X + (size_t)(m0 + row) * DIN + xk4 * 4);
            xs[(xk4 * 4 + 0) * BM1 + row] = v.x;
            xs[(xk4 * 4 + 1) * BM1 + row] = v.y;
            xs[(xk4 * 4 + 2) * BM1 + row] = v.z;
            xs[(xk4 * 4 + 3) * BM1 + row] = v.w;
        }
#pragma unroll
        for (int it = 0; it < 10; it++) {
            int n = wn + 16 * it;
            ws[wk * BN1 + n] = (n < N1) ? Wm[(size_t)n * DIN + wk] : 0.0f;
        }
    }
    __syncthreads();

    const int NKT = DIN / BK1;   // 64
    for (int kt = 0; kt < NKT; kt++) {
        const int cur = kt & 1;
        const int nxt = cur ^ 1;
        float* xsc = xs + cur * BK1 * BM1;
        float* wsc = ws + cur * BK1 * BN1;

        // prefetch next tile into registers
        float4 xv4[2];
        float  wv[10];
        if (kt + 1 < NKT) {
            int kk = (kt + 1) * BK1;
#pragma unroll
            for (int it = 0; it < 2; it++) {
                int row = xrow + 64 * it;
                xv4[it] = *(const float4*)(X + (size_t)(m0 + row) * DIN + kk + xk4 * 4);
            }
#pragma unroll
            for (int it = 0; it < 10; it++) {
                int n = wn + 16 * it;
                wv[it] = (n < N1) ? Wm[(size_t)n * DIN + kk + wk] : 0.0f;
            }
        }

        // compute on current buffer
#pragma unroll
        for (int k = 0; k < BK1; k++) {
            unsigned long long xv[4];
#pragma unroll
            for (int i = 0; i < 4; i++)
                xv[i] = *(const unsigned long long*)&xsc[k * BM1 + ty * 8 + 2 * i];
#pragma unroll
            for (int j = 0; j < 10; j++) {
                unsigned long long wd = dup2(wsc[k * BN1 + tx * 10 + j]);
#pragma unroll
                for (int i = 0; i < 4; i++) fma2(acc[i][j], xv[i], wd);
            }
        }

        // store prefetched tile to the other buffer
        if (kt + 1 < NKT) {
            float* xsn = xs + nxt * BK1 * BM1;
            float* wsn = ws + nxt * BK1 * BN1;
#pragma unroll
            for (int it = 0; it < 2; it++) {
                int row = xrow + 64 * it;
                xsn[(xk4 * 4 + 0) * BM1 + row] = xv4[it].x;
                xsn[(xk4 * 4 + 1) * BM1 + row] = xv4[it].y;
                xsn[(xk4 * 4 + 2) * BM1 + row] = xv4[it].z;
                xsn[(xk4 * 4 + 3) * BM1 + row] = xv4[it].w;
            }
#pragma unroll
            for (int it = 0; it < 10; it++) {
                int n = wn + 16 * it;
                wsn[wk * BN1 + n] = wv[it];
            }
        }
        __syncthreads();
    }

    // ================= epilogue: autocorrelation (block-local) ============
    // alias smem: px[128][65], py[128][65], contrib[128][64], inv_r0[128]
    float* px      = sm;
    float* py      = sm + 128 * 65;
    float* contrib = sm + 2 * 128 * 65;
    float* inv_r0  = sm + 2 * 128 * 65 + 128 * 64;

    // scatter p (+bias) into px/py
#pragma unroll
    for (int j = 0; j < 10; j++) {
        int col = tx * 10 + j;
        if (col < N1) {
            float bv = __ldg(bias + col);
#pragma unroll
            for (int i = 0; i < 4; i++) {
                int rl = ty * 8 + 2 * i;
                float v0 = lo32(acc[i][j]) + bv;
                float v1 = hi32(acc[i][j]) + bv;
                if (col < L) {
                    px[rl * 65 + col]       = v0;
                    px[(rl + 1) * 65 + col] = v1;
                } else {
                    py[rl * 65 + (col - L)]       = v0;
                    py[(rl + 1) * 65 + (col - L)] = v1;
                }
            }
        }
    }
    __syncthreads();

    // pass 1: r0 per row (threads 0..127)
    if (tid < 128) {
        const float* pxr = px + tid * 65;
        const float* pyr = py + tid * 65;
        float s = 0.0f;
        for (int j = 0; j < L; j++) s += pxr[j] * pxr[j] + pyr[j] * pyr[j];
        inv_r0[tid] = 1.0f / s;
    }
    __syncthreads();

    // pass 2: lags 1..64 for all 128 rows (8192 tasks / 256 threads)
    for (int t = tid; t < 128 * 64; t += 256) {
        int row = t >> 6;
        int lag = 1 + (t & 63);
        const float* pxr = px + row * 65;
        const float* pyr = py + row * 65;
        float sre = 0.0f, sim = 0.0f;
        int n = L - lag;
        for (int j = 0; j < n; j++) {
            float xj = pxr[j], yj = pyr[j];
            float xk = pxr[j + lag], yk = pyr[j + lag];
            sre += xk * xj + yk * yj;
            sim += yk * xj - xk * yj;
        }
        float ir = inv_r0[row];
        float cr = sre * ir;
        float ci = sim * ir;
        size_t base = (size_t)(m0 + row) * K2;
        g_coef[base + (lag - 1)]     = cr;
        g_coef[base + F + (lag - 1)] = ci;
        contrib[row * 64 + (lag - 1)] = cr * g_CS[lag - 1] - ci * g_SS[lag - 1];
    }
    __syncthreads();

    // pass 3: deterministic row sums -> invS
    if (tid < 128) {
        const float* cb = contrib + tid * 64;
        float S = 0.5f * (float)D;
        for (int k = 0; k < 64; k++) S += cb[k];
        g_invS[m0 + tid] = 1.0f / S;
    }
}

// ============================================================
// Kernel 2: like = coef @ T (+0.5), fused normalize + log epilogue
// M=rows, N=512, K=128. BM=128, BN=128, BK=16, 256 threads, 8x8 microtile
// Double-buffered smem, register prefetch, full K unroll.
// ============================================================
#define BM2 128
#define BN2 128
#define BK2 16

__global__ void __launch_bounds__(256) gemm2_kernel(float* __restrict__ out) {
    __shared__ float as_[2][BK2][BM2];
    __shared__ float bs[2][BK2][BN2];
    const int tid = threadIdx.x;
    const int tx = tid & 15;
    const int ty = tid >> 4;
    const int m0 = blockIdx.x * BM2;
    const int n0 = blockIdx.y * BN2;

    unsigned long long acc[4][8];
#pragma unroll
    for (int i = 0; i < 4; i++)
#pragma unroll
        for (int j = 0; j < 8; j++) acc[i][j] = 0ULL;

    const int arow = tid >> 2;   // 0..63 (+64)
    const int ak4  = tid & 3;
    const int bk   = tid >> 5;   // 0..7 (+8)
    const int bn4  = tid & 31;

    // preload tile 0
    {
#pragma unroll
        for (int it = 0; it < 2; it++) {
            int row = arow + 64 * it;
            float4 v = *(const float4*)(g_coef + (size_t)(m0 + row) * K2 + ak4 * 4);
            as_[0][ak4 * 4 + 0][row] = v.x;
            as_[0][ak4 * 4 + 1][row] = v.y;
            as_[0][ak4 * 4 + 2][row] = v.z;
            as_[0][ak4 * 4 + 3][row] = v.w;
        }
#pragma unroll
        for (int it = 0; it < 2; it++) {
            int k = bk + 8 * it;
            float4 v = *(const float4*)(g_T + (size_t)k * D + n0 + bn4 * 4);
            *(float4*)&bs[0][k][bn4 * 4] = v;
        }
    }
    __syncthreads();

#pragma unroll
    for (int kt = 0; kt < K2 / BK2; kt++) {   // 8 iterations
        const int cur = kt & 1;
        const int nxt = cur ^ 1;

        float4 av4[2], bv4[2];
        if (kt + 1 < K2 / BK2) {
            int kk = (kt + 1) * BK2;
#pragma unroll
            for (int it = 0; it < 2; it++) {
                int row = arow + 64 * it;
                av4[it] = *(const float4*)(g_coef + (size_t)(m0 + row) * K2 + kk + ak4 * 4);
            }
#pragma unroll
            for (int it = 0; it < 2; it++) {
                int k = bk + 8 * it;
                bv4[it] = *(const float4*)(g_T + (size_t)(kk + k) * D + n0 + bn4 * 4);
            }
        }

#pragma unroll
        for (int k = 0; k < BK2; k++) {
            unsigned long long av[4];
#pragma unroll
            for (int i = 0; i < 4; i++)
                av[i] = *(const unsigned long long*)&as_[cur][k][ty * 8 + 2 * i];
#pragma unroll
            for (int j = 0; j < 8; j++) {
                unsigned long long wd = dup2(bs[cur][k][tx * 8 + j]);
#pragma unroll
                for (int i = 0; i < 4; i++) fma2(acc[i][j], av[i], wd);
            }
        }

        if (kt + 1 < K2 / BK2) {
#pragma unroll
            for (int it = 0; it < 2; it++) {
                int row = arow + 64 * it;
                as_[nxt][ak4 * 4 + 0][row] = av4[it].x;
                as_[nxt][ak4 * 4 + 1][row] = av4[it].y;
                as_[nxt][ak4 * 4 + 2][row] = av4[it].z;
                as_[nxt][ak4 * 4 + 3][row] = av4[it].w;
            }
#pragma unroll
            for (int it = 0; it < 2; it++) {
                int k = bk + 8 * it;
                *(float4*)&bs[nxt][k][bn4 * 4] = bv4[it];
            }
        }
        __syncthreads();
    }

    // Epilogue: logits = log((0.5 + acc) * invS + 1e-5)
#pragma unroll
    for (int i = 0; i < 4; i++) {
        int r = m0 + ty * 8 + 2 * i;
        float is0 = g_invS[r];
        float is1 = g_invS[r + 1];
        float o0[8], o1[8];
#pragma unroll
        for (int j = 0; j < 8; j++) {
            o0[j] = __logf(fmaf(lo32(acc[i][j]) + 0.5f, is0, 1e-5f));
            o1[j] = __logf(fmaf(hi32(acc[i][j]) + 0.5f, is1, 1e-5f));
        }
        float* p0 = out + (size_t)r * D + n0 + tx * 8;
        *(float4*)(p0 + 0) = make_float4(o0[0], o0[1], o0[2], o0[3]);
        *(float4*)(p0 + 4) = make_float4(o0[4], o0[5], o0[6], o0[7]);
        float* p1 = out + (size_t)(r + 1) * D + n0 + tx * 8;
        *(float4*)(p1 + 0) = make_float4(o1[0], o1[1], o1[2], o1[3]);
        *(float4*)(p1 + 4) = make_float4(o1[4], o1[5], o1[6], o1[7]);
    }
}

extern "C" void kernel_launch(void* const* d_in, const int* in_sizes, int n_in,
                              void* d_out, int out_size) {
    const float* X = (const float*)d_in[0];     // batch [16,4096,1024]
    const float* Wm = (const float*)d_in[1];    // W [130,1024]
    const float* bias = (const float*)d_in[2];  // b [130]
    float* out = (float*)d_out;                 // [16,4096,512] f32

    const int rows = in_sizes[0] / DIN;         // 65536

    static bool attr_set = false;
    if (!attr_set) {
        cudaFuncSetAttribute(gemm1_fused_kernel,
                             cudaFuncAttributeMaxDynamicSharedMemorySize, SM1_BYTES);
        attr_set = true;
    }

    table_kernel<<<F, D>>>();
    gemm1_fused_kernel<<<rows / BM1, 256, SM1_BYTES>>>(X, Wm, bias);
    gemm2_kernel<<<dim3(rows / BM2, D / BN2), 256>>>(out);
}

// round 8
// speedup vs baseline: 2.2882x; 2.2528x over previous
#include <cuda_runtime.h>
#include <cuda_bf16.h>
#include <cstdint>

// Problem constants (fixed shapes)
constexpr int DIN      = 1024;   // input dim
constexpr int L        = 65;     // NUM_FREQ + 1
constexpr int N1       = 130;    // 2L (GEMM1 output cols)
constexpr int F        = 64;     // NUM_FREQ
constexpr int K2       = 128;    // 2F (GEMM2 reduction)
constexpr int D        = 512;    // DIM_OUTPUT
constexpr int ROWS_MAX = 65536;  // 16 * 4096

// GEMM1 mma tiling
constexpr int NTILES  = 17;            // 136 cols / 8
constexpr int KSTEPS  = 64;            // 1024 / 16
constexpr int KSTAGE  = 4;             // ksteps per smem stage
constexpr int NSTAGES = KSTEPS / KSTAGE;   // 16
constexpr int KSTEP_U32 = 2 * NTILES * 32 * 2;       // 2176 u32 = 8704 B per kstep
constexpr int STAGE_BYTES = KSTAGE * KSTEP_U32 * 4;  // 34816
constexpr int STAGE_U16B  = STAGE_BYTES / 16;        // 2176 16B-chunks

// Scratch (static device globals — no runtime allocation)
__device__ float g_coef[(size_t)ROWS_MAX * K2];   // [c.re | c.im]
__device__ float g_T[(size_t)K2 * D];             // rows 0..63: cos, 64..127: -sin
__device__ float g_CS[F];
__device__ float g_SS[F];
__device__ float g_invS[ROWS_MAX];
// B fragments in exact mma per-lane layout: [ks][hi/lo][ntile][lane][2]
__device__ __align__(16) uint32_t g_Bfrag[(size_t)KSTEPS * KSTEP_U32];

// ---- helpers ----
__device__ __forceinline__ uint32_t smem_u32(const void* p) {
    uint32_t a;
    asm("{ .reg .u64 t; cvta.to.shared.u64 t, %1; cvt.u32.u64 %0, t; }" : "=r"(a) : "l"(p));
    return a;
}
__device__ __forceinline__ uint32_t pack_hi(float2 v) {
    __nv_bfloat162 h = __floats2bfloat162_rn(v.x, v.y);
    return *(uint32_t*)&h;
}
__device__ __forceinline__ uint32_t pack_lo(float2 v, uint32_t hp) {
    __nv_bfloat162 h = *(__nv_bfloat162*)&hp;
    float rx = v.x - __bfloat162float(h.x);
    float ry = v.y - __bfloat162float(h.y);
    __nv_bfloat162 lo = __floats2bfloat162_rn(rx, ry);
    return *(uint32_t*)&lo;
}
__device__ __forceinline__ void mma_bf16(float* c, uint32_t a0, uint32_t a1,
                                         uint32_t a2, uint32_t a3,
                                         uint32_t b0, uint32_t b1) {
    asm volatile(
        "mma.sync.aligned.m16n8k16.row.col.f32.bf16.bf16.f32 "
        "{%0,%1,%2,%3}, {%4,%5,%6,%7}, {%8,%9}, {%0,%1,%2,%3};"
        : "+f"(c[0]), "+f"(c[1]), "+f"(c[2]), "+f"(c[3])
        : "r"(a0), "r"(a1), "r"(a2), "r"(a3), "r"(b0), "r"(b1));
}
#define CPA16(dst_u32, src_ptr) \
    asm volatile("cp.async.cg.shared.global [%0], [%1], 16;" :: "r"(dst_u32), "l"(src_ptr) : "memory")
#define CPA_COMMIT() asm volatile("cp.async.commit_group;" ::: "memory")
#define CPA_WAIT1()  asm volatile("cp.async.wait_group 1;" ::: "memory")
#define CPA_WAIT0()  asm volatile("cp.async.wait_group 0;" ::: "memory")

// ---- packed f32x2 helpers (sm_100 family baseline) for GEMM2 ----
__device__ __forceinline__ void fma2(unsigned long long& d, unsigned long long a,
                                     unsigned long long b) {
    asm("fma.rn.f32x2 %0, %1, %2, %0;" : "+l"(d) : "l"(a), "l"(b));
}
__device__ __forceinline__ unsigned long long dup2(float w) {
    unsigned long long r;
    asm("mov.b64 %0, {%1, %1};" : "=l"(r) : "f"(w));
    return r;
}
__device__ __forceinline__ float lo32(unsigned long long v) {
    return __uint_as_float((unsigned)(v & 0xffffffffu));
}
__device__ __forceinline__ float hi32(unsigned long long v) {
    return __uint_as_float((unsigned)(v >> 32));
}

// ============================================================
// Kernel 0: build cos/sin table + column sums
// ============================================================
__global__ void table_kernel() {
    const int f = blockIdx.x;
    const int d = threadIdx.x;
    float center = -1.0f + (2 * d + 1) * (1.0f / 512.0f);
    float arg = center * (float)(f + 1);
    float s, c;
    sincospif(arg, &s, &c);
    g_T[(size_t)f * D + d] = c;
    g_T[(size_t)(F + f) * D + d] = -s;

    __shared__ float sc[512], ss[512];
    sc[d] = c;
    ss[d] = s;
    __syncthreads();
    for (int off = 256; off > 0; off >>= 1) {
        if (d < off) {
            sc[d] += sc[d + off];
            ss[d] += ss[d + off];
        }
        __syncthreads();
    }
    if (d == 0) {
        g_CS[f] = sc[0];
        g_SS[f] = ss[0];
    }
}

// ============================================================
// Kernel 0b: W -> bf16 hi/lo mma B-fragments in per-lane layout
// grid (64 ksteps), block (544 = 17 ntiles * 32 lanes)
// B frag (col-major, m16n8k16): b0 = {W[n][kc], W[n][kc+1]},
// b1 = {W[n][kc+8], W[n][kc+9]}, n = nt*8 + lane/4, kc = ks*16 + (lane%4)*2
// ============================================================
__global__ void wprep_kernel(const float* __restrict__ Wm) {
    const int ks = blockIdx.x;
    const int nt = threadIdx.x >> 5;
    const int lane = threadIdx.x & 31;
    const int n = nt * 8 + (lane >> 2);
    const int kc = ks * 16 + (lane & 3) * 2;
    float2 wa = make_float2(0.f, 0.f), wb = make_float2(0.f, 0.f);
    if (n < N1) {
        const float* wr = Wm + (size_t)n * DIN;
        wa = make_float2(wr[kc], wr[kc + 1]);
        wb = make_float2(wr[kc + 8], wr[kc + 9]);
    }
    uint32_t h0 = pack_hi(wa), h1 = pack_hi(wb);
    uint32_t l0 = pack_lo(wa, h0), l1 = pack_lo(wb, h1);
    size_t bh = ((((size_t)ks * 2 + 0) * NTILES + nt) * 32 + lane) * 2;
    size_t bl = ((((size_t)ks * 2 + 1) * NTILES + nt) * 32 + lane) * 2;
    g_Bfrag[bh] = h0;
    g_Bfrag[bh + 1] = h1;
    g_Bfrag[bl] = l0;
    g_Bfrag[bl + 1] = l1;
}

// ============================================================
// Kernel 1 (HMMA): p = X @ W^T + b  -> autocorr -> coef + invS
// 256 threads, 8 warps; warp w owns rows w*16..w*16+15, all 136 cols.
// Split-bf16: acc += Ahi*Bhi + Ahi*Blo + Alo*Bhi.
// A frags loaded directly from global X (each element read once).
// B frags cp.async'd from pre-layout staging, double-buffered.
// ============================================================
// smem offsets
constexpr int SM_B0   = 0;
constexpr int SM_B1   = STAGE_BYTES;                 // 34816
// epilogue overlay (over B buffers):
constexpr int SM_PX    = 0;                          // 128*65 f32 = 33280
constexpr int SM_PY    = 33280;                      // -> 66560
constexpr int SM_CONTR = 66560;                      // 128*64 f32 -> 99328
constexpr int SM_INVR  = 99328;                      // 128 f32 -> 99840
constexpr int SM_BIAS  = 99840;                      // 136 f32 -> 100384
constexpr int SM1_BYTES = 100384 + 64;

__global__ void __launch_bounds__(256)
gemm1_mma_kernel(const float* __restrict__ X, const float* __restrict__ bias) {
    extern __shared__ char sm[];
    const uint32_t sb = smem_u32(sm);
    const int tid = threadIdx.x;
    const int w = tid >> 5;
    const int lane = tid & 31;
    const int m0 = blockIdx.x * 128;

    // bias to smem (pad 130..135 with 0)
    if (tid < 136) ((float*)(sm + SM_BIAS))[tid] = (tid < N1) ? bias[tid] : 0.0f;

    float acc[NTILES][4];
#pragma unroll
    for (int nt = 0; nt < NTILES; nt++)
#pragma unroll
        for (int i = 0; i < 4; i++) acc[nt][i] = 0.0f;

    // per-lane X row base pointers (A fragment addressing)
    const float* xb1 = X + (size_t)(m0 + w * 16 + (lane >> 2)) * DIN + (lane & 3) * 2;
    const float* xb2 = xb1 + 8 * DIN;

    const char* gB = (const char*)g_Bfrag;

    // prologue: stage 0
    for (int i = tid; i < STAGE_U16B; i += 256)
        CPA16(sb + SM_B0 + i * 16, gB + (size_t)i * 16);
    CPA_COMMIT();

    for (int s = 0; s < NSTAGES; s++) {
        __syncthreads();   // everyone done computing stage s-1 (its buffer = next dst)
        if (s + 1 < NSTAGES) {
            uint32_t dst = sb + ((s + 1) & 1 ? SM_B1 : SM_B0);
            const char* src = gB + (size_t)(s + 1) * STAGE_BYTES;
            for (int i = tid; i < STAGE_U16B; i += 256)
                CPA16(dst + i * 16, src + (size_t)i * 16);
            CPA_COMMIT();
            CPA_WAIT1();
        } else {
            CPA_WAIT0();
        }
        __syncthreads();

        const char* bbuf = sm + ((s & 1) ? SM_B1 : SM_B0);
#pragma unroll
        for (int ksl = 0; ksl < KSTAGE; ksl++) {
            const int kk = (s * KSTAGE + ksl) * 16;
            // A fragments from global, split bf16
            float2 v1a = *(const float2*)(xb1 + kk);
            float2 v1b = *(const float2*)(xb1 + kk + 8);
            float2 v2a = *(const float2*)(xb2 + kk);
            float2 v2b = *(const float2*)(xb2 + kk + 8);
            uint32_t ah0 = pack_hi(v1a), ah1 = pack_hi(v2a);
            uint32_t ah2 = pack_hi(v1b), ah3 = pack_hi(v2b);
            uint32_t al0 = pack_lo(v1a, ah0), al1 = pack_lo(v2a, ah1);
            uint32_t al2 = pack_lo(v1b, ah2), al3 = pack_lo(v2b, ah3);

            const char* kbase = bbuf + ksl * (KSTEP_U32 * 4) + lane * 8;
#pragma unroll
            for (int nt = 0; nt < NTILES; nt++) {
                uint2 bh = *(const uint2*)(kbase + nt * 256);
                uint2 bl = *(const uint2*)(kbase + NTILES * 256 + nt * 256);
                mma_bf16(acc[nt], ah0, ah1, ah2, ah3, bh.x, bh.y);
                mma_bf16(acc[nt], ah0, ah1, ah2, ah3, bl.x, bl.y);
                mma_bf16(acc[nt], al0, al1, al2, al3, bh.x, bh.y);
            }
        }
    }
    __syncthreads();   // all warps done with B smem before overlaying px/py

    // ---- scatter acc (+bias) into px/py ----
    float* px = (float*)(sm + SM_PX);
    float* py = (float*)(sm + SM_PY);
    float* sbias = (float*)(sm + SM_BIAS);
    {
        const int r1 = w * 16 + (lane >> 2);   // local rows r1, r1+8
        const int cb = (lane & 3) * 2;
#pragma unroll
        for (int nt = 0; nt < NTILES; nt++) {
            int col0 = nt * 8 + cb;
#pragma unroll
            for (int h = 0; h < 2; h++) {       // col0, col0+1
                int col = col0 + h;
                if (col < N1) {
                    float bv = sbias[col];
                    float v0 = acc[nt][h] + bv;       // row r1
                    float v1 = acc[nt][2 + h] + bv;   // row r1+8
                    if (col < L) {
                        px[r1 * 65 + col] = v0;
                        px[(r1 + 8) * 65 + col] = v1;
                    } else {
                        py[r1 * 65 + (col - L)] = v0;
                        py[(r1 + 8) * 65 + (col - L)] = v1;
                    }
                }
            }
        }
    }
    __syncthreads();

    // ---- autocorrelation (block-local) ----
    float* contrib = (float*)(sm + SM_CONTR);
    float* inv_r0 = (float*)(sm + SM_INVR);

    if (tid < 128) {
        const float* pxr = px + tid * 65;
        const float* pyr = py + tid * 65;
        float s = 0.0f;
        for (int j = 0; j < L; j++) s += pxr[j] * pxr[j] + pyr[j] * pyr[j];
        inv_r0[tid] = 1.0f / s;
    }
    __syncthreads();

    for (int t = tid; t < 128 * 64; t += 256) {
        int row = t >> 6;
        int lag = 1 + (t & 63);
        const float* pxr = px + row * 65;
        const float* pyr = py + row * 65;
        float sre = 0.0f, sim = 0.0f;
        int n = L - lag;
        for (int j = 0; j < n; j++) {
            float xj = pxr[j], yj = pyr[j];
            float xk = pxr[j + lag], yk = pyr[j + lag];
            sre += xk * xj + yk * yj;
            sim += yk * xj - xk * yj;
        }
        float ir = inv_r0[row];
        float cr = sre * ir;
        float ci = sim * ir;
        size_t base = (size_t)(m0 + row) * K2;
        g_coef[base + (lag - 1)]     = cr;
        g_coef[base + F + (lag - 1)] = ci;
        contrib[row * 64 + (lag - 1)] = cr * g_CS[lag - 1] - ci * g_SS[lag - 1];
    }
    __syncthreads();

    if (tid < 128) {
        const float* cb = contrib + tid * 64;
        float S = 0.5f * (float)D;
        for (int k = 0; k < 64; k++) S += cb[k];
        g_invS[m0 + tid] = 1.0f / S;
    }
}

// ============================================================
// Kernel 2: like = coef @ T (+0.5), fused normalize + log epilogue
// (f32x2 version, unchanged)
// ============================================================
#define BM2 128
#define BN2 128
#define BK2 16

__global__ void __launch_bounds__(256) gemm2_kernel(float* __restrict__ out) {
    __shared__ float as_[2][BK2][BM2];
    __shared__ float bs[2][BK2][BN2];
    const int tid = threadIdx.x;
    const int tx = tid & 15;
    const int ty = tid >> 4;
    const int m0 = blockIdx.x * BM2;
    const int n0 = blockIdx.y * BN2;

    unsigned long long acc[4][8];
#pragma unroll
    for (int i = 0; i < 4; i++)
#pragma unroll
        for (int j = 0; j < 8; j++) acc[i][j] = 0ULL;

    const int arow = tid >> 2;
    const int ak4  = tid & 3;
    const int bk   = tid >> 5;
    const int bn4  = tid & 31;

    {
#pragma unroll
        for (int it = 0; it < 2; it++) {
            int row = arow + 64 * it;
            float4 v = *(const float4*)(g_coef + (size_t)(m0 + row) * K2 + ak4 * 4);
            as_[0][ak4 * 4 + 0][row] = v.x;
            as_[0][ak4 * 4 + 1][row] = v.y;
            as_[0][ak4 * 4 + 2][row] = v.z;
            as_[0][ak4 * 4 + 3][row] = v.w;
        }
#pragma unroll
        for (int it = 0; it < 2; it++) {
            int k = bk + 8 * it;
            float4 v = *(const float4*)(g_T + (size_t)k * D + n0 + bn4 * 4);
            *(float4*)&bs[0][k][bn4 * 4] = v;
        }
    }
    __syncthreads();

#pragma unroll
    for (int kt = 0; kt < K2 / BK2; kt++) {
        const int cur = kt & 1;
        const int nxt = cur ^ 1;

        float4 av4[2], bv4[2];
        if (kt + 1 < K2 / BK2) {
            int kk = (kt + 1) * BK2;
#pragma unroll
            for (int it = 0; it < 2; it++) {
                int row = arow + 64 * it;
                av4[it] = *(const float4*)(g_coef + (size_t)(m0 + row) * K2 + kk + ak4 * 4);
            }
#pragma unroll
            for (int it = 0; it < 2; it++) {
                int k = bk + 8 * it;
                bv4[it] = *(const float4*)(g_T + (size_t)(kk + k) * D + n0 + bn4 * 4);
            }
        }

#pragma unroll
        for (int k = 0; k < BK2; k++) {
            unsigned long long av[4];
#pragma unroll
            for (int i = 0; i < 4; i++)
                av[i] = *(const unsigned long long*)&as_[cur][k][ty * 8 + 2 * i];
#pragma unroll
            for (int j = 0; j < 8; j++) {
                unsigned long long wd = dup2(bs[cur][k][tx * 8 + j]);
#pragma unroll
                for (int i = 0; i < 4; i++) fma2(acc[i][j], av[i], wd);
            }
        }

        if (kt + 1 < K2 / BK2) {
#pragma unroll
            for (int it = 0; it < 2; it++) {
                int row = arow + 64 * it;
                as_[nxt][ak4 * 4 + 0][row] = av4[it].x;
                as_[nxt][ak4 * 4 + 1][row] = av4[it].y;
                as_[nxt][ak4 * 4 + 2][row] = av4[it].z;
                as_[nxt][ak4 * 4 + 3][row] = av4[it].w;
            }
#pragma unroll
            for (int it = 0; it < 2; it++) {
                int k = bk + 8 * it;
                *(float4*)&bs[nxt][k][bn4 * 4] = bv4[it];
            }
        }
        __syncthreads();
    }

#pragma unroll
    for (int i = 0; i < 4; i++) {
        int r = m0 + ty * 8 + 2 * i;
        float is0 = g_invS[r];
        float is1 = g_invS[r + 1];
        float o0[8], o1[8];
#pragma unroll
        for (int j = 0; j < 8; j++) {
            o0[j] = __logf(fmaf(lo32(acc[i][j]) + 0.5f, is0, 1e-5f));
            o1[j] = __logf(fmaf(hi32(acc[i][j]) + 0.5f, is1, 1e-5f));
        }
        float* p0 = out + (size_t)r * D + n0 + tx * 8;
        *(float4*)(p0 + 0) = make_float4(o0[0], o0[1], o0[2], o0[3]);
        *(float4*)(p0 + 4) = make_float4(o0[4], o0[5], o0[6], o0[7]);
        float* p1 = out + (size_t)(r + 1) * D + n0 + tx * 8;
        *(float4*)(p1 + 0) = make_float4(o1[0], o1[1], o1[2], o1[3]);
        *(float4*)(p1 + 4) = make_float4(o1[4], o1[5], o1[6], o1[7]);
    }
}

extern "C" void kernel_launch(void* const* d_in, const int* in_sizes, int n_in,
                              void* d_out, int out_size) {
    const float* X = (const float*)d_in[0];     // batch [16,4096,1024]
    const float* Wm = (const float*)d_in[1];    // W [130,1024]
    const float* bias = (const float*)d_in[2];  // b [130]
    float* out = (float*)d_out;                 // [16,4096,512] f32

    const int rows = in_sizes[0] / DIN;         // 65536

    static bool attr_set = false;
    if (!attr_set) {
        cudaFuncSetAttribute(gemm1_mma_kernel,
                             cudaFuncAttributeMaxDynamicSharedMemorySize, SM1_BYTES);
        attr_set = true;
    }

    table_kernel<<<F, D>>>();
    wprep_kernel<<<KSTEPS, NTILES * 32>>>(Wm);
    gemm1_mma_kernel<<<rows / 128, 256, SM1_BYTES>>>(X, bias);
    gemm2_kernel<<<dim3(rows / BM2, D / BN2), 256>>>(out);
}

// round 9
// speedup vs baseline: 2.8316x; 1.2375x over previous
#include <cuda_runtime.h>
#include <cuda_bf16.h>
#include <cstdint>

// Problem constants (fixed shapes)
constexpr int DIN      = 1024;   // input dim
constexpr int L        = 65;     // NUM_FREQ + 1
constexpr int N1       = 130;    // 2L (GEMM1 output cols)
constexpr int F        = 64;     // NUM_FREQ
constexpr int K2       = 128;    // 2F (GEMM2 reduction)
constexpr int D        = 512;    // DIM_OUTPUT
constexpr int ROWS_MAX = 65536;  // 16 * 4096

// GEMM1 mma tiling
constexpr int NTILES  = 17;            // 136 cols / 8
constexpr int KSTEPS  = 64;            // 1024 / 16
constexpr int KSTAGE  = 4;             // ksteps per smem stage
constexpr int NSTAGES = KSTEPS / KSTAGE;   // 16
constexpr int KSTEP_U32 = 2 * NTILES * 32 * 2;       // 2176 u32 = 8704 B per kstep
constexpr int STAGE_BYTES = KSTAGE * KSTEP_U32 * 4;  // 34816
constexpr int STAGE_U16B  = STAGE_BYTES / 16;        // 2176 16B-chunks

// GEMM2 mma tiling: per CTA 128 rows x 128 cols, K=128 (8 ksteps), 16 ntiles
constexpr int G2_NT   = 16;
constexpr int G2_KS   = 8;
constexpr int TFRAG_U32_PER_NT = G2_KS * 2 * 32 * 2;     // 1024 u32 per (global) ntile
constexpr int TFRAG_U32 = 64 * TFRAG_U32_PER_NT;         // 65536 u32 = 256 KB total
constexpr int SM2_U32  = G2_NT * TFRAG_U32_PER_NT;       // 16384 u32 = 64 KB per CTA
constexpr int SM2_BYTES = SM2_U32 * 4;

// Scratch (static device globals — no runtime allocation)
__device__ __align__(16) __nv_bfloat16 g_coefh[(size_t)ROWS_MAX * K2];
__device__ __align__(16) __nv_bfloat16 g_coefl[(size_t)ROWS_MAX * K2];
__device__ float g_CS[F];
__device__ float g_SS[F];
__device__ float g_invS[ROWS_MAX];
// GEMM1 B fragments: [ks][hi/lo][ntile][lane][2]
__device__ __align__(16) uint32_t g_Bfrag[(size_t)KSTEPS * KSTEP_U32];
// GEMM2 B fragments (T table): [nt][ks][hi/lo][lane][2]
__device__ __align__(16) uint32_t g_Tfrag[(size_t)TFRAG_U32];

// ---- helpers ----
__device__ __forceinline__ uint32_t smem_u32(const void* p) {
    uint32_t a;
    asm("{ .reg .u64 t; cvta.to.shared.u64 t, %1; cvt.u32.u64 %0, t; }" : "=r"(a) : "l"(p));
    return a;
}
__device__ __forceinline__ uint32_t pack_hi(float2 v) {
    __nv_bfloat162 h = __floats2bfloat162_rn(v.x, v.y);
    return *(uint32_t*)&h;
}
__device__ __forceinline__ uint32_t pack_lo(float2 v, uint32_t hp) {
    __nv_bfloat162 h = *(__nv_bfloat162*)&hp;
    float rx = v.x - __bfloat162float(h.x);
    float ry = v.y - __bfloat162float(h.y);
    __nv_bfloat162 lo = __floats2bfloat162_rn(rx, ry);
    return *(uint32_t*)&lo;
}
__device__ __forceinline__ void mma_bf16(float* c, uint32_t a0, uint32_t a1,
                                         uint32_t a2, uint32_t a3,
                                         uint32_t b0, uint32_t b1) {
    asm volatile(
        "mma.sync.aligned.m16n8k16.row.col.f32.bf16.bf16.f32 "
        "{%0,%1,%2,%3}, {%4,%5,%6,%7}, {%8,%9}, {%0,%1,%2,%3};"
        : "+f"(c[0]), "+f"(c[1]), "+f"(c[2]), "+f"(c[3])
        : "r"(a0), "r"(a1), "r"(a2), "r"(a3), "r"(b0), "r"(b1));
}
#define CPA16(dst_u32, src_ptr) \
    asm volatile("cp.async.cg.shared.global [%0], [%1], 16;" :: "r"(dst_u32), "l"(src_ptr) : "memory")
#define CPA_COMMIT() asm volatile("cp.async.commit_group;" ::: "memory")
#define CPA_WAIT1()  asm volatile("cp.async.wait_group 1;" ::: "memory")
#define CPA_WAIT0()  asm volatile("cp.async.wait_group 0;" ::: "memory")

// ============================================================
// Kernel 0: column sums of cos/sin table (CS/SS only)
// ============================================================
__global__ void table_kernel() {
    const int f = blockIdx.x;
    const int d = threadIdx.x;
    float center = -1.0f + (2 * d + 1) * (1.0f / 512.0f);
    float arg = center * (float)(f + 1);
    float s, c;
    sincospif(arg, &s, &c);

    __shared__ float sc[512], ss[512];
    sc[d] = c;
    ss[d] = s;
    __syncthreads();
    for (int off = 256; off > 0; off >>= 1) {
        if (d < off) {
            sc[d] += sc[d + off];
            ss[d] += ss[d + off];
        }
        __syncthreads();
    }
    if (d == 0) {
        g_CS[f] = sc[0];
        g_SS[f] = ss[0];
    }
}

// ============================================================
// Kernel 0b: W -> bf16 hi/lo mma B-fragments (GEMM1)
// ============================================================
__global__ void wprep_kernel(const float* __restrict__ Wm) {
    const int ks = blockIdx.x;
    const int nt = threadIdx.x >> 5;
    const int lane = threadIdx.x & 31;
    const int n = nt * 8 + (lane >> 2);
    const int kc = ks * 16 + (lane & 3) * 2;
    float2 wa = make_float2(0.f, 0.f), wb = make_float2(0.f, 0.f);
    if (n < N1) {
        const float* wr = Wm + (size_t)n * DIN;
        wa = make_float2(wr[kc], wr[kc + 1]);
        wb = make_float2(wr[kc + 8], wr[kc + 9]);
    }
    uint32_t h0 = pack_hi(wa), h1 = pack_hi(wb);
    uint32_t l0 = pack_lo(wa, h0), l1 = pack_lo(wb, h1);
    size_t bh = ((((size_t)ks * 2 + 0) * NTILES + nt) * 32 + lane) * 2;
    size_t bl = ((((size_t)ks * 2 + 1) * NTILES + nt) * 32 + lane) * 2;
    g_Bfrag[bh] = h0;
    g_Bfrag[bh + 1] = h1;
    g_Bfrag[bl] = l0;
    g_Bfrag[bl + 1] = l1;
}

// ============================================================
// Kernel 0c: T table -> bf16 hi/lo mma B-fragments (GEMM2)
// grid (64 nt), block (256 = 8 ks x 32 lanes)
// T[k][n]: k<64 -> cos(center_n*pi*(k+1)); k>=64 -> -sin(center_n*pi*(k-63))
// layout: [nt][ks][h][lane][2]
// ============================================================
__device__ __forceinline__ float tval(int k, float center) {
    float s, c;
    if (k < F) {
        sincospif(center * (float)(k + 1), &s, &c);
        return c;
    } else {
        sincospif(center * (float)(k - F + 1), &s, &c);
        return -s;
    }
}
__global__ void tprep_kernel() {
    const int nt = blockIdx.x;
    const int ks = threadIdx.x >> 5;
    const int lane = threadIdx.x & 31;
    const int n = nt * 8 + (lane >> 2);
    const int kc = ks * 16 + (lane & 3) * 2;
    float center = -1.0f + (2 * n + 1) * (1.0f / 512.0f);
    float2 va = make_float2(tval(kc, center), tval(kc + 1, center));
    float2 vb = make_float2(tval(kc + 8, center), tval(kc + 9, center));
    uint32_t h0 = pack_hi(va), h1 = pack_hi(vb);
    uint32_t l0 = pack_lo(va, h0), l1 = pack_lo(vb, h1);
    size_t base = ((size_t)nt * G2_KS + ks) * 2;
    size_t bh = (base * 32 + lane) * 2;
    size_t bl = ((base + 1) * 32 + lane) * 2;
    g_Tfrag[bh] = h0;
    g_Tfrag[bh + 1] = h1;
    g_Tfrag[bl] = l0;
    g_Tfrag[bl + 1] = l1;
}

// ============================================================
// Kernel 1 (HMMA): p = X @ W^T + b  -> autocorr -> coef(bf16 hi/lo) + invS
// ============================================================
constexpr int SM_B0   = 0;
constexpr int SM_B1   = STAGE_BYTES;                 // 34816
constexpr int SM_PX    = 0;                          // 128*65 f32 = 33280
constexpr int SM_PY    = 33280;                      // -> 66560
constexpr int SM_CONTR = 66560;                      // 128*64 f32 -> 99328
constexpr int SM_INVR  = 99328;                      // 128 f32 -> 99840
constexpr int SM_BIAS  = 99840;                      // 136 f32 -> 100384
constexpr int SM1_BYTES = 100384 + 64;

__global__ void __launch_bounds__(256)
gemm1_mma_kernel(const float* __restrict__ X, const float* __restrict__ bias) {
    extern __shared__ char sm[];
    const uint32_t sb = smem_u32(sm);
    const int tid = threadIdx.x;
    const int w = tid >> 5;
    const int lane = tid & 31;
    const int m0 = blockIdx.x * 128;

    if (tid < 136) ((float*)(sm + SM_BIAS))[tid] = (tid < N1) ? bias[tid] : 0.0f;

    float acc[NTILES][4];
#pragma unroll
    for (int nt = 0; nt < NTILES; nt++)
#pragma unroll
        for (int i = 0; i < 4; i++) acc[nt][i] = 0.0f;

    const float* xb1 = X + (size_t)(m0 + w * 16 + (lane >> 2)) * DIN + (lane & 3) * 2;
    const float* xb2 = xb1 + 8 * DIN;

    const char* gB = (const char*)g_Bfrag;

    for (int i = tid; i < STAGE_U16B; i += 256)
        CPA16(sb + SM_B0 + i * 16, gB + (size_t)i * 16);
    CPA_COMMIT();

    for (int s = 0; s < NSTAGES; s++) {
        __syncthreads();
        if (s + 1 < NSTAGES) {
            uint32_t dst = sb + ((s + 1) & 1 ? SM_B1 : SM_B0);
            const char* src = gB + (size_t)(s + 1) * STAGE_BYTES;
            for (int i = tid; i < STAGE_U16B; i += 256)
                CPA16(dst + i * 16, src + (size_t)i * 16);
            CPA_COMMIT();
            CPA_WAIT1();
        } else {
            CPA_WAIT0();
        }
        __syncthreads();

        const char* bbuf = sm + ((s & 1) ? SM_B1 : SM_B0);
#pragma unroll
        for (int ksl = 0; ksl < KSTAGE; ksl++) {
            const int kk = (s * KSTAGE + ksl) * 16;
            float2 v1a = *(const float2*)(xb1 + kk);
            float2 v1b = *(const float2*)(xb1 + kk + 8);
            float2 v2a = *(const float2*)(xb2 + kk);
            float2 v2b = *(const float2*)(xb2 + kk + 8);
            uint32_t ah0 = pack_hi(v1a), ah1 = pack_hi(v2a);
            uint32_t ah2 = pack_hi(v1b), ah3 = pack_hi(v2b);
            uint32_t al0 = pack_lo(v1a, ah0), al1 = pack_lo(v2a, ah1);
            uint32_t al2 = pack_lo(v1b, ah2), al3 = pack_lo(v2b, ah3);

            const char* kbase = bbuf + ksl * (KSTEP_U32 * 4) + lane * 8;
#pragma unroll
            for (int nt = 0; nt < NTILES; nt++) {
                uint2 bh = *(const uint2*)(kbase + nt * 256);
                uint2 bl = *(const uint2*)(kbase + NTILES * 256 + nt * 256);
                mma_bf16(acc[nt], ah0, ah1, ah2, ah3, bh.x, bh.y);
                mma_bf16(acc[nt], ah0, ah1, ah2, ah3, bl.x, bl.y);
                mma_bf16(acc[nt], al0, al1, al2, al3, bh.x, bh.y);
            }
        }
    }
    __syncthreads();

    // ---- scatter acc (+bias) into px/py ----
    float* px = (float*)(sm + SM_PX);
    float* py = (float*)(sm + SM_PY);
    float* sbias = (float*)(sm + SM_BIAS);
    {
        const int r1 = w * 16 + (lane >> 2);
        const int cb = (lane & 3) * 2;
#pragma unroll
        for (int nt = 0; nt < NTILES; nt++) {
            int col0 = nt * 8 + cb;
#pragma unroll
            for (int h = 0; h < 2; h++) {
                int col = col0 + h;
                if (col < N1) {
                    float bv = sbias[col];
                    float v0 = acc[nt][h] + bv;
                    float v1 = acc[nt][2 + h] + bv;
                    if (col < L) {
                        px[r1 * 65 + col] = v0;
                        px[(r1 + 8) * 65 + col] = v1;
                    } else {
                        py[r1 * 65 + (col - L)] = v0;
                        py[(r1 + 8) * 65 + (col - L)] = v1;
                    }
                }
            }
        }
    }
    __syncthreads();

    // ---- autocorrelation (block-local) ----
    float* contrib = (float*)(sm + SM_CONTR);
    float* inv_r0 = (float*)(sm + SM_INVR);

    if (tid < 128) {
        const float* pxr = px + tid * 65;
        const float* pyr = py + tid * 65;
        float s = 0.0f;
        for (int j = 0; j < L; j++) s += pxr[j] * pxr[j] + pyr[j] * pyr[j];
        inv_r0[tid] = 1.0f / s;
    }
    __syncthreads();

    for (int t = tid; t < 128 * 64; t += 256) {
        int row = t >> 6;
        int lag = 1 + (t & 63);
        const float* pxr = px + row * 65;
        const float* pyr = py + row * 65;
        float sre = 0.0f, sim = 0.0f;
        int n = L - lag;
        for (int j = 0; j < n; j++) {
            float xj = pxr[j], yj = pyr[j];
            float xk = pxr[j + lag], yk = pyr[j + lag];
            sre += xk * xj + yk * yj;
            sim += yk * xj - xk * yj;
        }
        float ir = inv_r0[row];
        float cr = sre * ir;
        float ci = sim * ir;
        size_t base = (size_t)(m0 + row) * K2;
        // store bf16 hi/lo split
        __nv_bfloat16 crh = __float2bfloat16(cr);
        __nv_bfloat16 cih = __float2bfloat16(ci);
        g_coefh[base + (lag - 1)]     = crh;
        g_coefh[base + F + (lag - 1)] = cih;
        g_coefl[base + (lag - 1)]     = __float2bfloat16(cr - __bfloat162float(crh));
        g_coefl[base + F + (lag - 1)] = __float2bfloat16(ci - __bfloat162float(cih));
        contrib[row * 64 + (lag - 1)] = cr * g_CS[lag - 1] - ci * g_SS[lag - 1];
    }
    __syncthreads();

    if (tid < 128) {
        const float* cb = contrib + tid * 64;
        float S = 0.5f * (float)D;
        for (int k = 0; k < 64; k++) S += cb[k];
        g_invS[m0 + tid] = 1.0f / S;
    }
}

// ============================================================
// Kernel 2 (HMMA): like = coef @ T (+0.5) -> log epilogue
// grid (rows/128, 4), 256 threads / 8 warps.
// Warp w: rows w*16..+15; CTA col block nb*128, 16 ntiles.
// B (T fragments) loaded once to smem; A from global bf16 hi/lo.
// ============================================================
__global__ void __launch_bounds__(256)
gemm2_mma_kernel(float* __restrict__ out) {
    extern __shared__ char sm[];
    uint32_t* smB = (uint32_t*)sm;
    const int tid = threadIdx.x;
    const int w = tid >> 5;
    const int lane = tid & 31;
    const int m0 = blockIdx.x * 128;
    const int nb = blockIdx.y;

    // load this CTA's 64 KB T-fragment slice
    {
        const uint4* src = (const uint4*)(g_Tfrag + (size_t)nb * SM2_U32);
        uint4* dst = (uint4*)smB;
        for (int i = tid; i < SM2_U32 / 4; i += 256) dst[i] = src[i];
    }
    __syncthreads();

    float acc[G2_NT][4];
#pragma unroll
    for (int nt = 0; nt < G2_NT; nt++)
#pragma unroll
        for (int i = 0; i < 4; i++) acc[nt][i] = 0.0f;

    const int r1 = m0 + w * 16 + (lane >> 2);
    const __nv_bfloat16* ch1 = g_coefh + (size_t)r1 * K2;
    const __nv_bfloat16* ch2 = ch1 + 8 * K2;
    const __nv_bfloat16* cl1 = g_coefl + (size_t)r1 * K2;
    const __nv_bfloat16* cl2 = cl1 + 8 * K2;
    const int kc0 = (lane & 3) * 2;

#pragma unroll
    for (int ks = 0; ks < G2_KS; ks++) {
        const int kc = ks * 16 + kc0;
        uint32_t ah0 = *(const uint32_t*)(ch1 + kc);
        uint32_t ah1 = *(const uint32_t*)(ch2 + kc);
        uint32_t ah2 = *(const uint32_t*)(ch1 + kc + 8);
        uint32_t ah3 = *(const uint32_t*)(ch2 + kc + 8);
        uint32_t al0 = *(const uint32_t*)(cl1 + kc);
        uint32_t al1 = *(const uint32_t*)(cl2 + kc);
        uint32_t al2 = *(const uint32_t*)(cl1 + kc + 8);
        uint32_t al3 = *(const uint32_t*)(cl2 + kc + 8);
#pragma unroll
        for (int nt = 0; nt < G2_NT; nt++) {
            const uint32_t* p = smB + (((nt * G2_KS + ks) * 2) * 32 + lane) * 2;
            uint2 bh = *(const uint2*)p;
            uint2 bl = *(const uint2*)(p + 64);
            mma_bf16(acc[nt], ah0, ah1, ah2, ah3, bh.x, bh.y);
            mma_bf16(acc[nt], ah0, ah1, ah2, ah3, bl.x, bl.y);
            mma_bf16(acc[nt], al0, al1, al2, al3, bh.x, bh.y);
        }
    }

    // epilogue: logits = log((0.5 + acc) * invS + 1e-5)
    const float is0 = g_invS[r1];
    const float is1 = g_invS[r1 + 8];
    float* o0 = out + (size_t)r1 * D + nb * 128 + kc0;
    float* o1 = o0 + 8 * (size_t)D;
#pragma unroll
    for (int nt = 0; nt < G2_NT; nt++) {
        float2 u0, u1;
        u0.x = __logf(fmaf(acc[nt][0] + 0.5f, is0, 1e-5f));
        u0.y = __logf(fmaf(acc[nt][1] + 0.5f, is0, 1e-5f));
        u1.x = __logf(fmaf(acc[nt][2] + 0.5f, is1, 1e-5f));
        u1.y = __logf(fmaf(acc[nt][3] + 0.5f, is1, 1e-5f));
        *(float2*)(o0 + nt * 8) = u0;
        *(float2*)(o1 + nt * 8) = u1;
    }
}

extern "C" void kernel_launch(void* const* d_in, const int* in_sizes, int n_in,
                              void* d_out, int out_size) {
    const float* X = (const float*)d_in[0];     // batch [16,4096,1024]
    const float* Wm = (const float*)d_in[1];    // W [130,1024]
    const float* bias = (const float*)d_in[2];  // b [130]
    float* out = (float*)d_out;                 // [16,4096,512] f32

    const int rows = in_sizes[0] / DIN;         // 65536

    static bool attr_set = false;
    if (!attr_set) {
        cudaFuncSetAttribute(gemm1_mma_kernel,
                             cudaFuncAttributeMaxDynamicSharedMemorySize, SM1_BYTES);
        cudaFuncSetAttribute(gemm2_mma_kernel,
                             cudaFuncAttributeMaxDynamicSharedMemorySize, SM2_BYTES);
        attr_set = true;
    }

    table_kernel<<<F, D>>>();
    wprep_kernel<<<KSTEPS, NTILES * 32>>>(Wm);
    tprep_kernel<<<64, 256>>>();
    gemm1_mma_kernel<<<rows / 128, 256, SM1_BYTES>>>(X, bias);
    gemm2_mma_kernel<<<dim3(rows / 128, 4), 256, SM2_BYTES>>>(out);
}

// round 10
// speedup vs baseline: 2.9343x; 1.0363x over previous
#include <cuda_runtime.h>
#include <cuda_bf16.h>
#include <cstdint>

// Problem constants (fixed shapes)
constexpr int DIN      = 1024;   // input dim
constexpr int L        = 65;     // NUM_FREQ + 1
constexpr int N1       = 130;    // 2L (GEMM1 output cols)
constexpr int F        = 64;     // NUM_FREQ
constexpr int K2       = 128;    // 2F (GEMM2 reduction)
constexpr int D        = 512;    // DIM_OUTPUT
constexpr int ROWS_MAX = 65536;  // 16 * 4096

// GEMM1 mma tiling
constexpr int NTILES  = 17;            // 136 cols / 8
constexpr int KSTEPS  = 64;            // 1024 / 16, one kstep per pipeline stage
constexpr int KSTEP_U32 = 2 * NTILES * 32 * 2;       // 2176 u32 = 8704 B per kstep (B frags)

// gemm1 pipeline: 4-buffer ring, 1 kstep per stage
constexpr int G1_BST   = 8704;             // B bytes per stage
constexpr int G1_XROWB = 96;               // X smem row stride (24 floats, 2-way conflicts max)
constexpr int G1_XST   = 128 * G1_XROWB;   // 12288 B per stage
constexpr int G1_STAGE = G1_BST + G1_XST;  // 20992
constexpr int G1_NBUF  = 4;                // 83968 B total ring
constexpr int G1_BCH   = G1_BST / 16;      // 544 16B chunks
constexpr int G1_XCH   = G1_XST / 16;      // 768? no: 12288/16 = 768 -- but only 512 carry data
constexpr int G1_XDATA = 128 * 4;          // 512 real chunks (4 x 16B per row)
constexpr int G1_CHUNKS = G1_BCH + G1_XDATA;   // 1056

// GEMM2 mma tiling: per CTA 128 rows x 128 cols, K=128 (8 ksteps), 16 ntiles
constexpr int G2_NT   = 16;
constexpr int G2_KS   = 8;
constexpr int TFRAG_U32_PER_NT = G2_KS * 2 * 32 * 2;     // 1024 u32 per (global) ntile
constexpr int TFRAG_U32 = 64 * TFRAG_U32_PER_NT;         // 65536 u32 = 256 KB total
constexpr int SM2_U32  = G2_NT * TFRAG_U32_PER_NT;       // 16384 u32 = 64 KB per CTA
constexpr int SM2_BYTES = SM2_U32 * 4;

// Scratch (static device globals — no runtime allocation)
__device__ __align__(16) __nv_bfloat16 g_coefh[(size_t)ROWS_MAX * K2];
__device__ __align__(16) __nv_bfloat16 g_coefl[(size_t)ROWS_MAX * K2];
__device__ float g_CS[F];
__device__ float g_SS[F];
__device__ float g_invS[ROWS_MAX];
// GEMM1 B fragments: [ks][hi/lo][ntile][lane][2]
__device__ __align__(16) uint32_t g_Bfrag[(size_t)KSTEPS * KSTEP_U32];
// GEMM2 B fragments (T table): [nt][ks][hi/lo][lane][2]
__device__ __align__(16) uint32_t g_Tfrag[(size_t)TFRAG_U32];

// ---- helpers ----
__device__ __forceinline__ uint32_t smem_u32(const void* p) {
    uint32_t a;
    asm("{ .reg .u64 t; cvta.to.shared.u64 t, %1; cvt.u32.u64 %0, t; }" : "=r"(a) : "l"(p));
    return a;
}
__device__ __forceinline__ uint32_t pack_hi(float2 v) {
    __nv_bfloat162 h = __floats2bfloat162_rn(v.x, v.y);
    return *(uint32_t*)&h;
}
__device__ __forceinline__ uint32_t pack_lo(float2 v, uint32_t hp) {
    __nv_bfloat162 h = *(__nv_bfloat162*)&hp;
    float rx = v.x - __bfloat162float(h.x);
    float ry = v.y - __bfloat162float(h.y);
    __nv_bfloat162 lo = __floats2bfloat162_rn(rx, ry);
    return *(uint32_t*)&lo;
}
__device__ __forceinline__ void mma_bf16(float* c, uint32_t a0, uint32_t a1,
                                         uint32_t a2, uint32_t a3,
                                         uint32_t b0, uint32_t b1) {
    asm volatile(
        "mma.sync.aligned.m16n8k16.row.col.f32.bf16.bf16.f32 "
        "{%0,%1,%2,%3}, {%4,%5,%6,%7}, {%8,%9}, {%0,%1,%2,%3};"
        : "+f"(c[0]), "+f"(c[1]), "+f"(c[2]), "+f"(c[3])
        : "r"(a0), "r"(a1), "r"(a2), "r"(a3), "r"(b0), "r"(b1));
}
#define CPA16(dst_u32, src_ptr) \
    asm volatile("cp.async.cg.shared.global [%0], [%1], 16;" :: "r"(dst_u32), "l"(src_ptr) : "memory")
#define CPA_COMMIT() asm volatile("cp.async.commit_group;" ::: "memory")
#define CPA_WAIT2()  asm volatile("cp.async.wait_group 2;" ::: "memory")
#define CPA_WAIT1()  asm volatile("cp.async.wait_group 1;" ::: "memory")
#define CPA_WAIT0()  asm volatile("cp.async.wait_group 0;" ::: "memory")

// ============================================================
// Kernel 0: column sums of cos/sin table (CS/SS only)
// ============================================================
__global__ void table_kernel() {
    const int f = blockIdx.x;
    const int d = threadIdx.x;
    float center = -1.0f + (2 * d + 1) * (1.0f / 512.0f);
    float arg = center * (float)(f + 1);
    float s, c;
    sincospif(arg, &s, &c);

    __shared__ float sc[512], ss[512];
    sc[d] = c;
    ss[d] = s;
    __syncthreads();
    for (int off = 256; off > 0; off >>= 1) {
        if (d < off) {
            sc[d] += sc[d + off];
            ss[d] += ss[d + off];
        }
        __syncthreads();
    }
    if (d == 0) {
        g_CS[f] = sc[0];
        g_SS[f] = ss[0];
    }
}

// ============================================================
// Kernel 0b: W -> bf16 hi/lo mma B-fragments (GEMM1)
// ============================================================
__global__ void wprep_kernel(const float* __restrict__ Wm) {
    const int ks = blockIdx.x;
    const int nt = threadIdx.x >> 5;
    const int lane = threadIdx.x & 31;
    const int n = nt * 8 + (lane >> 2);
    const int kc = ks * 16 + (lane & 3) * 2;
    float2 wa = make_float2(0.f, 0.f), wb = make_float2(0.f, 0.f);
    if (n < N1) {
        const float* wr = Wm + (size_t)n * DIN;
        wa = make_float2(wr[kc], wr[kc + 1]);
        wb = make_float2(wr[kc + 8], wr[kc + 9]);
    }
    uint32_t h0 = pack_hi(wa), h1 = pack_hi(wb);
    uint32_t l0 = pack_lo(wa, h0), l1 = pack_lo(wb, h1);
    size_t bh = ((((size_t)ks * 2 + 0) * NTILES + nt) * 32 + lane) * 2;
    size_t bl = ((((size_t)ks * 2 + 1) * NTILES + nt) * 32 + lane) * 2;
    g_Bfrag[bh] = h0;
    g_Bfrag[bh + 1] = h1;
    g_Bfrag[bl] = l0;
    g_Bfrag[bl + 1] = l1;
}

// ============================================================
// Kernel 0c: T table -> bf16 hi/lo mma B-fragments (GEMM2)
// ============================================================
__device__ __forceinline__ float tval(int k, float center) {
    float s, c;
    if (k < F) {
        sincospif(center * (float)(k + 1), &s, &c);
        return c;
    } else {
        sincospif(center * (float)(k - F + 1), &s, &c);
        return -s;
    }
}
__global__ void tprep_kernel() {
    const int nt = blockIdx.x;
    const int ks = threadIdx.x >> 5;
    const int lane = threadIdx.x & 31;
    const int n = nt * 8 + (lane >> 2);
    const int kc = ks * 16 + (lane & 3) * 2;
    float center = -1.0f + (2 * n + 1) * (1.0f / 512.0f);
    float2 va = make_float2(tval(kc, center), tval(kc + 1, center));
    float2 vb = make_float2(tval(kc + 8, center), tval(kc + 9, center));
    uint32_t h0 = pack_hi(va), h1 = pack_hi(vb);
    uint32_t l0 = pack_lo(va, h0), l1 = pack_lo(vb, h1);
    size_t base = ((size_t)nt * G2_KS + ks) * 2;
    size_t bh = (base * 32 + lane) * 2;
    size_t bl = ((base + 1) * 32 + lane) * 2;
    g_Tfrag[bh] = h0;
    g_Tfrag[bh + 1] = h1;
    g_Tfrag[bl] = l0;
    g_Tfrag[bl + 1] = l1;
}

// ============================================================
// Kernel 1 (HMMA, cp.async pipelined): p = X@W^T + b -> autocorr
// 4-stage ring: each stage = 1 kstep of B-frags (8704B) + X tile (12288B).
// All global traffic is cp.async; compute reads smem only.
// ============================================================
constexpr int SM_PX    = 0;                          // 128*65 f32 = 33280
constexpr int SM_PY    = 33280;                      // -> 66560
constexpr int SM_CONTR = 66560;                      // 128*64 f32 -> 99328
constexpr int SM_INVR  = 99328;                      // 128 f32 -> 99840
constexpr int SM_BIAS  = 99840;                      // 136 f32 -> 100384
constexpr int SM1_BYTES = 100384 + 64;

__global__ void __launch_bounds__(256)
gemm1_mma_kernel(const float* __restrict__ X, const float* __restrict__ bias) {
    extern __shared__ char sm[];
    const uint32_t sb = smem_u32(sm);
    const int tid = threadIdx.x;
    const int w = tid >> 5;
    const int lane = tid & 31;
    const int m0 = blockIdx.x * 128;

    if (tid < 136) ((float*)(sm + SM_BIAS))[tid] = (tid < N1) ? bias[tid] : 0.0f;

    float acc[NTILES][4];
#pragma unroll
    for (int nt = 0; nt < NTILES; nt++)
#pragma unroll
        for (int i = 0; i < 4; i++) acc[nt][i] = 0.0f;

    const char* gB = (const char*)g_Bfrag;

    // stage copy: B chunk ids [0,544), X chunk ids [544,1056)
    auto copy_stage = [&](int s, int buf) {
        const uint32_t dstb = sb + buf * G1_STAGE;
        const char* srcB = gB + (size_t)s * G1_BST;
#pragma unroll
        for (int it = 0; it < 5; it++) {
            int i = tid + 256 * it;
            if (i < G1_BCH) {
                CPA16(dstb + i * 16, srcB + i * 16);
            } else if (i < G1_CHUNKS) {
                int j = i - G1_BCH;
                int row = j >> 2;
                int c4 = j & 3;
                const float* src = X + (size_t)(m0 + row) * DIN + s * 16 + c4 * 4;
                CPA16(dstb + G1_BST + row * G1_XROWB + c4 * 16, src);
            }
        }
    };

    // prologue: stages 0..2
    copy_stage(0, 0); CPA_COMMIT();
    copy_stage(1, 1); CPA_COMMIT();
    copy_stage(2, 2); CPA_COMMIT();

    const int xoff = (w * 16 + (lane >> 2)) * G1_XROWB + (lane & 3) * 8;

    for (int s = 0; s < KSTEPS; s++) {
        if (s < KSTEPS - 2)      { CPA_WAIT2(); }
        else if (s == KSTEPS - 2) { CPA_WAIT1(); }
        else                      { CPA_WAIT0(); }
        __syncthreads();
        if (s + 3 < KSTEPS) {
            copy_stage(s + 3, (s + 3) & 3);
            CPA_COMMIT();
        }

        const char* bb = sm + (s & 3) * G1_STAGE;
        // A fragments from smem X tile
        const char* xb = bb + G1_BST + xoff;
        float2 v1a = *(const float2*)(xb);
        float2 v1b = *(const float2*)(xb + 32);
        float2 v2a = *(const float2*)(xb + 8 * G1_XROWB);
        float2 v2b = *(const float2*)(xb + 8 * G1_XROWB + 32);
        uint32_t ah0 = pack_hi(v1a), ah1 = pack_hi(v2a);
        uint32_t ah2 = pack_hi(v1b), ah3 = pack_hi(v2b);
        uint32_t al0 = pack_lo(v1a, ah0), al1 = pack_lo(v2a, ah1);
        uint32_t al2 = pack_lo(v1b, ah2), al3 = pack_lo(v2b, ah3);

        const char* kbase = bb + lane * 8;
#pragma unroll
        for (int nt = 0; nt < NTILES; nt++) {
            uint2 bh = *(const uint2*)(kbase + nt * 256);
            uint2 bl = *(const uint2*)(kbase + NTILES * 256 + nt * 256);
            mma_bf16(acc[nt], ah0, ah1, ah2, ah3, bh.x, bh.y);
            mma_bf16(acc[nt], ah0, ah1, ah2, ah3, bl.x, bl.y);
            mma_bf16(acc[nt], al0, al1, al2, al3, bh.x, bh.y);
        }
    }
    __syncthreads();   // all warps done with ring before overlaying px/py

    // ---- scatter acc (+bias) into px/py ----
    float* px = (float*)(sm + SM_PX);
    float* py = (float*)(sm + SM_PY);
    float* sbias = (float*)(sm + SM_BIAS);
    {
        const int r1 = w * 16 + (lane >> 2);
        const int cb = (lane & 3) * 2;
#pragma unroll
        for (int nt = 0; nt < NTILES; nt++) {
            int col0 = nt * 8 + cb;
#pragma unroll
            for (int h = 0; h < 2; h++) {
                int col = col0 + h;
                if (col < N1) {
                    float bv = sbias[col];
                    float v0 = acc[nt][h] + bv;
                    float v1 = acc[nt][2 + h] + bv;
                    if (col < L) {
                        px[r1 * 65 + col] = v0;
                        px[(r1 + 8) * 65 + col] = v1;
                    } else {
                        py[r1 * 65 + (col - L)] = v0;
                        py[(r1 + 8) * 65 + (col - L)] = v1;
                    }
                }
            }
        }
    }
    __syncthreads();

    // ---- autocorrelation (block-local) ----
    float* contrib = (float*)(sm + SM_CONTR);
    float* inv_r0 = (float*)(sm + SM_INVR);

    if (tid < 128) {
        const float* pxr = px + tid * 65;
        const float* pyr = py + tid * 65;
        float s = 0.0f;
        for (int j = 0; j < L; j++) s += pxr[j] * pxr[j] + pyr[j] * pyr[j];
        inv_r0[tid] = 1.0f / s;
    }
    __syncthreads();

    for (int t = tid; t < 128 * 64; t += 256) {
        int row = t >> 6;
        int lag = 1 + (t & 63);
        const float* pxr = px + row * 65;
        const float* pyr = py + row * 65;
        float sre = 0.0f, sim = 0.0f;
        int n = L - lag;
        for (int j = 0; j < n; j++) {
            float xj = pxr[j], yj = pyr[j];
            float xk = pxr[j + lag], yk = pyr[j + lag];
            sre += xk * xj + yk * yj;
            sim += yk * xj - xk * yj;
        }
        float ir = inv_r0[row];
        float cr = sre * ir;
        float ci = sim * ir;
        size_t base = (size_t)(m0 + row) * K2;
        __nv_bfloat16 crh = __float2bfloat16(cr);
        __nv_bfloat16 cih = __float2bfloat16(ci);
        g_coefh[base + (lag - 1)]     = crh;
        g_coefh[base + F + (lag - 1)] = cih;
        g_coefl[base + (lag - 1)]     = __float2bfloat16(cr - __bfloat162float(crh));
        g_coefl[base + F + (lag - 1)] = __float2bfloat16(ci - __bfloat162float(cih));
        contrib[row * 64 + (lag - 1)] = cr * g_CS[lag - 1] - ci * g_SS[lag - 1];
    }
    __syncthreads();

    if (tid < 128) {
        const float* cb = contrib + tid * 64;
        float S = 0.5f * (float)D;
        for (int k = 0; k < 64; k++) S += cb[k];
        g_invS[m0 + tid] = 1.0f / S;
    }
}

// ============================================================
// Kernel 2 (HMMA): like = coef @ T (+0.5) -> log epilogue
// ============================================================
__global__ void __launch_bounds__(256)
gemm2_mma_kernel(float* __restrict__ out) {
    extern __shared__ char sm[];
    uint32_t* smB = (uint32_t*)sm;
    const int tid = threadIdx.x;
    const int w = tid >> 5;
    const int lane = tid & 31;
    const int m0 = blockIdx.x * 128;
    const int nb = blockIdx.y;

    {
        const uint4* src = (const uint4*)(g_Tfrag + (size_t)nb * SM2_U32);
        uint4* dst = (uint4*)smB;
        for (int i = tid; i < SM2_U32 / 4; i += 256) dst[i] = src[i];
    }
    __syncthreads();

    float acc[G2_NT][4];
#pragma unroll
    for (int nt = 0; nt < G2_NT; nt++)
#pragma unroll
        for (int i = 0; i < 4; i++) acc[nt][i] = 0.0f;

    const int r1 = m0 + w * 16 + (lane >> 2);
    const __nv_bfloat16* ch1 = g_coefh + (size_t)r1 * K2;
    const __nv_bfloat16* ch2 = ch1 + 8 * K2;
    const __nv_bfloat16* cl1 = g_coefl + (size_t)r1 * K2;
    const __nv_bfloat16* cl2 = cl1 + 8 * K2;
    const int kc0 = (lane & 3) * 2;

#pragma unroll
    for (int ks = 0; ks < G2_KS; ks++) {
        const int kc = ks * 16 + kc0;
        uint32_t ah0 = *(const uint32_t*)(ch1 + kc);
        uint32_t ah1 = *(const uint32_t*)(ch2 + kc);
        uint32_t ah2 = *(const uint32_t*)(ch1 + kc + 8);
        uint32_t ah3 = *(const uint32_t*)(ch2 + kc + 8);
        uint32_t al0 = *(const uint32_t*)(cl1 + kc);
        uint32_t al1 = *(const uint32_t*)(cl2 + kc);
        uint32_t al2 = *(const uint32_t*)(cl1 + kc + 8);
        uint32_t al3 = *(const uint32_t*)(cl2 + kc + 8);
#pragma unroll
        for (int nt = 0; nt < G2_NT; nt++) {
            const uint32_t* p = smB + (((nt * G2_KS + ks) * 2) * 32 + lane) * 2;
            uint2 bh = *(const uint2*)p;
            uint2 bl = *(const uint2*)(p + 64);
            mma_bf16(acc[nt], ah0, ah1, ah2, ah3, bh.x, bh.y);
            mma_bf16(acc[nt], ah0, ah1, ah2, ah3, bl.x, bl.y);
            mma_bf16(acc[nt], al0, al1, al2, al3, bh.x, bh.y);
        }
    }

    const float is0 = g_invS[r1];
    const float is1 = g_invS[r1 + 8];
    float* o0 = out + (size_t)r1 * D + nb * 128 + kc0;
    float* o1 = o0 + 8 * (size_t)D;
#pragma unroll
    for (int nt = 0; nt < G2_NT; nt++) {
        float2 u0, u1;
        u0.x = __logf(fmaf(acc[nt][0] + 0.5f, is0, 1e-5f));
        u0.y = __logf(fmaf(acc[nt][1] + 0.5f, is0, 1e-5f));
        u1.x = __logf(fmaf(acc[nt][2] + 0.5f, is1, 1e-5f));
        u1.y = __logf(fmaf(acc[nt][3] + 0.5f, is1, 1e-5f));
        *(float2*)(o0 + nt * 8) = u0;
        *(float2*)(o1 + nt * 8) = u1;
    }
}

extern "C" void kernel_launch(void* const* d_in, const int* in_sizes, int n_in,
                              void* d_out, int out_size) {
    const float* X = (const float*)d_in[0];     // batch [16,4096,1024]
    const float* Wm = (const float*)d_in[1];    // W [130,1024]
    const float* bias = (const float*)d_in[2];  // b [130]
    float* out = (float*)d_out;                 // [16,4096,512] f32

    const int rows = in_sizes[0] / DIN;         // 65536

    static bool attr_set = false;
    if (!attr_set) {
        cudaFuncSetAttribute(gemm1_mma_kernel,
                             cudaFuncAttributeMaxDynamicSharedMemorySize, SM1_BYTES);
        cudaFuncSetAttribute(gemm2_mma_kernel,
                             cudaFuncAttributeMaxDynamicSharedMemorySize, SM2_BYTES);
        attr_set = true;
    }

    table_kernel<<<F, D>>>();
    wprep_kernel<<<KSTEPS, NTILES * 32>>>(Wm);
    tprep_kernel<<<64, 256>>>();
    gemm1_mma_kernel<<<rows / 128, 256, SM1_BYTES>>>(X, bias);
    gemm2_mma_kernel<<<dim3(rows / 128, 4), 256, SM2_BYTES>>>(out);
}

// round 11
// speedup vs baseline: 3.2437x; 1.1055x over previous
#include <cuda_runtime.h>
#include <cuda_bf16.h>
#include <cstdint>

// Problem constants (fixed shapes)
constexpr int DIN      = 1024;   // input dim
constexpr int L        = 65;     // NUM_FREQ + 1
constexpr int N1       = 130;    // 2L (GEMM1 output cols)
constexpr int F        = 64;     // NUM_FREQ
constexpr int K2       = 128;    // 2F (GEMM2 reduction)
constexpr int D        = 512;    // DIM_OUTPUT
constexpr int ROWS_MAX = 65536;  // 16 * 4096

// GEMM1 mma tiling: M=64 per CTA, ntiles split across warp halves
constexpr int NTILES  = 17;            // 136 cols / 8
constexpr int KSTEPS  = 64;            // 1024 / 16, one kstep per pipeline stage
constexpr int KSTEP_U32 = 2 * NTILES * 32 * 2;       // 2176 u32 = 8704 B per kstep (B frags)
constexpr int M_CTA   = 64;

// gemm1 pipeline: 4-buffer ring, 1 kstep per stage
constexpr int G1_BST   = 8704;             // B bytes per stage
constexpr int G1_XROWB = 96;               // X smem row stride (2-way conflicts max)
constexpr int G1_XST   = M_CTA * G1_XROWB; // 6144 B per stage
constexpr int G1_STAGE = G1_BST + G1_XST;  // 14848
constexpr int G1_BCH   = G1_BST / 16;      // 544 16B chunks
constexpr int G1_XDATA = M_CTA * 4;        // 256 chunks (4 x 16B per row)
constexpr int G1_CHUNKS = G1_BCH + G1_XDATA;   // 800

// GEMM2 mma tiling: per CTA 128 rows x 128 cols, K=128 (8 ksteps), 16 ntiles
constexpr int G2_NT   = 16;
constexpr int G2_KS   = 8;
constexpr int TFRAG_U32_PER_NT = G2_KS * 2 * 32 * 2;     // 1024 u32 per (global) ntile
constexpr int TFRAG_U32 = 64 * TFRAG_U32_PER_NT;         // 65536 u32 = 256 KB total
constexpr int SM2_U32  = G2_NT * TFRAG_U32_PER_NT;       // 16384 u32 = 64 KB per CTA
constexpr int SM2_BYTES = SM2_U32 * 4;

// Scratch (static device globals — no runtime allocation)
__device__ __align__(16) __nv_bfloat16 g_coefh[(size_t)ROWS_MAX * K2];
__device__ __align__(16) __nv_bfloat16 g_coefl[(size_t)ROWS_MAX * K2];
__device__ float g_CS[F];
__device__ float g_SS[F];
__device__ float g_invS[ROWS_MAX];
// GEMM1 B fragments: [ks][hi/lo][ntile][lane][2]
__device__ __align__(16) uint32_t g_Bfrag[(size_t)KSTEPS * KSTEP_U32];
// GEMM2 B fragments (T table): [nt][ks][hi/lo][lane][2]
__device__ __align__(16) uint32_t g_Tfrag[(size_t)TFRAG_U32];

// ---- helpers ----
__device__ __forceinline__ uint32_t smem_u32(const void* p) {
    uint32_t a;
    asm("{ .reg .u64 t; cvta.to.shared.u64 t, %1; cvt.u32.u64 %0, t; }" : "=r"(a) : "l"(p));
    return a;
}
__device__ __forceinline__ uint32_t pack_hi(float2 v) {
    __nv_bfloat162 h = __floats2bfloat162_rn(v.x, v.y);
    return *(uint32_t*)&h;
}
__device__ __forceinline__ uint32_t pack_lo(float2 v, uint32_t hp) {
    __nv_bfloat162 h = *(__nv_bfloat162*)&hp;
    float rx = v.x - __bfloat162float(h.x);
    float ry = v.y - __bfloat162float(h.y);
    __nv_bfloat162 lo = __floats2bfloat162_rn(rx, ry);
    return *(uint32_t*)&lo;
}
__device__ __forceinline__ void mma_bf16(float* c, uint32_t a0, uint32_t a1,
                                         uint32_t a2, uint32_t a3,
                                         uint32_t b0, uint32_t b1) {
    asm volatile(
        "mma.sync.aligned.m16n8k16.row.col.f32.bf16.bf16.f32 "
        "{%0,%1,%2,%3}, {%4,%5,%6,%7}, {%8,%9}, {%0,%1,%2,%3};"
        : "+f"(c[0]), "+f"(c[1]), "+f"(c[2]), "+f"(c[3])
        : "r"(a0), "r"(a1), "r"(a2), "r"(a3), "r"(b0), "r"(b1));
}
#define CPA16(dst_u32, src_ptr) \
    asm volatile("cp.async.cg.shared.global [%0], [%1], 16;" :: "r"(dst_u32), "l"(src_ptr) : "memory")
#define CPA_COMMIT() asm volatile("cp.async.commit_group;" ::: "memory")
#define CPA_WAIT2()  asm volatile("cp.async.wait_group 2;" ::: "memory")
#define CPA_WAIT1()  asm volatile("cp.async.wait_group 1;" ::: "memory")
#define CPA_WAIT0()  asm volatile("cp.async.wait_group 0;" ::: "memory")

// ============================================================
// Kernel 0: column sums of cos/sin table (CS/SS only)
// ============================================================
__global__ void table_kernel() {
    const int f = blockIdx.x;
    const int d = threadIdx.x;
    float center = -1.0f + (2 * d + 1) * (1.0f / 512.0f);
    float arg = center * (float)(f + 1);
    float s, c;
    sincospif(arg, &s, &c);

    __shared__ float sc[512], ss[512];
    sc[d] = c;
    ss[d] = s;
    __syncthreads();
    for (int off = 256; off > 0; off >>= 1) {
        if (d < off) {
            sc[d] += sc[d + off];
            ss[d] += ss[d + off];
        }
        __syncthreads();
    }
    if (d == 0) {
        g_CS[f] = sc[0];
        g_SS[f] = ss[0];
    }
}

// ============================================================
// Kernel 0b: W -> bf16 hi/lo mma B-fragments (GEMM1)
// ============================================================
__global__ void wprep_kernel(const float* __restrict__ Wm) {
    const int ks = blockIdx.x;
    const int nt = threadIdx.x >> 5;
    const int lane = threadIdx.x & 31;
    const int n = nt * 8 + (lane >> 2);
    const int kc = ks * 16 + (lane & 3) * 2;
    float2 wa = make_float2(0.f, 0.f), wb = make_float2(0.f, 0.f);
    if (n < N1) {
        const float* wr = Wm + (size_t)n * DIN;
        wa = make_float2(wr[kc], wr[kc + 1]);
        wb = make_float2(wr[kc + 8], wr[kc + 9]);
    }
    uint32_t h0 = pack_hi(wa), h1 = pack_hi(wb);
    uint32_t l0 = pack_lo(wa, h0), l1 = pack_lo(wb, h1);
    size_t bh = ((((size_t)ks * 2 + 0) * NTILES + nt) * 32 + lane) * 2;
    size_t bl = ((((size_t)ks * 2 + 1) * NTILES + nt) * 32 + lane) * 2;
    g_Bfrag[bh] = h0;
    g_Bfrag[bh + 1] = h1;
    g_Bfrag[bl] = l0;
    g_Bfrag[bl + 1] = l1;
}

// ============================================================
// Kernel 0c: T table -> bf16 hi/lo mma B-fragments (GEMM2)
// ============================================================
__device__ __forceinline__ float tval(int k, float center) {
    float s, c;
    if (k < F) {
        sincospif(center * (float)(k + 1), &s, &c);
        return c;
    } else {
        sincospif(center * (float)(k - F + 1), &s, &c);
        return -s;
    }
}
__global__ void tprep_kernel() {
    const int nt = blockIdx.x;
    const int ks = threadIdx.x >> 5;
    const int lane = threadIdx.x & 31;
    const int n = nt * 8 + (lane >> 2);
    const int kc = ks * 16 + (lane & 3) * 2;
    float center = -1.0f + (2 * n + 1) * (1.0f / 512.0f);
    float2 va = make_float2(tval(kc, center), tval(kc + 1, center));
    float2 vb = make_float2(tval(kc + 8, center), tval(kc + 9, center));
    uint32_t h0 = pack_hi(va), h1 = pack_hi(vb);
    uint32_t l0 = pack_lo(va, h0), l1 = pack_lo(vb, h1);
    size_t base = ((size_t)nt * G2_KS + ks) * 2;
    size_t bh = (base * 32 + lane) * 2;
    size_t bl = ((base + 1) * 32 + lane) * 2;
    g_Tfrag[bh] = h0;
    g_Tfrag[bh + 1] = h1;
    g_Tfrag[bl] = l0;
    g_Tfrag[bl + 1] = l1;
}

// ============================================================
// Kernel 1 (HMMA, cp.async pipelined, 3 CTAs/SM):
// M=64 rows/CTA; warps 0-3 handle ntiles 0-8, warps 4-7 ntiles 9-16,
// each warp-group covering all 64 rows (w&3 selects the 16-row slice).
// Epilogue: interleaved-complex autocorr.
// ============================================================
constexpr int SM_PZ    = 0;                          // 64 x 66 float2 = 33792
constexpr int SM_CONTR = 33792;                      // 64*64 f32 -> 50176
constexpr int SM_INVR  = 50176;                      // 64 f32 -> 50432
// ring occupies [0, 59392); overlay above fits inside
constexpr int SM_BIAS  = 4 * G1_STAGE;               // 59392, 136 f32 -> 59936
constexpr int SM1_BYTES = 59936 + 64;

__global__ void __launch_bounds__(256, 3)
gemm1_mma_kernel(const float* __restrict__ X, const float* __restrict__ bias) {
    extern __shared__ char sm[];
    const uint32_t sb = smem_u32(sm);
    const int tid = threadIdx.x;
    const int w = tid >> 5;
    const int lane = tid & 31;
    const int wg = w >> 2;           // 0: nt 0-8, 1: nt 9-16
    const int wr = w & 3;            // 16-row slice
    const int m0 = blockIdx.x * M_CTA;

    if (tid < 136) ((float*)(sm + SM_BIAS))[tid] = (tid < N1) ? bias[tid] : 0.0f;

    const int NT_MY = wg ? 8 : 9;    // ntiles this warp handles
    const int NT0   = wg ? 9 : 0;    // first ntile

    float acc[9][4];
#pragma unroll
    for (int nt = 0; nt < 9; nt++)
#pragma unroll
        for (int i = 0; i < 4; i++) acc[nt][i] = 0.0f;

    const char* gB = (const char*)g_Bfrag;

    // stage copy: B chunk ids [0,544), X chunk ids [544,800)
    auto copy_stage = [&](int s, int buf) {
        const uint32_t dstb = sb + buf * G1_STAGE;
        const char* srcB = gB + (size_t)s * G1_BST;
#pragma unroll
        for (int it = 0; it < 4; it++) {
            int i = tid + 256 * it;
            if (i < G1_BCH) {
                CPA16(dstb + i * 16, srcB + i * 16);
            } else if (i < G1_CHUNKS) {
                int j = i - G1_BCH;
                int row = j >> 2;
                int c4 = j & 3;
                const float* src = X + (size_t)(m0 + row) * DIN + s * 16 + c4 * 4;
                CPA16(dstb + G1_BST + row * G1_XROWB + c4 * 16, src);
            }
        }
    };

    copy_stage(0, 0); CPA_COMMIT();
    copy_stage(1, 1); CPA_COMMIT();
    copy_stage(2, 2); CPA_COMMIT();

    const int xoff = (wr * 16 + (lane >> 2)) * G1_XROWB + (lane & 3) * 8;

    for (int s = 0; s < KSTEPS; s++) {
        if (s < KSTEPS - 2)       { CPA_WAIT2(); }
        else if (s == KSTEPS - 2) { CPA_WAIT1(); }
        else                      { CPA_WAIT0(); }
        __syncthreads();
        if (s + 3 < KSTEPS) {
            copy_stage(s + 3, (s + 3) & 3);
            CPA_COMMIT();
        }

        const char* bb = sm + (s & 3) * G1_STAGE;
        const char* xb = bb + G1_BST + xoff;
        float2 v1a = *(const float2*)(xb);
        float2 v1b = *(const float2*)(xb + 32);
        float2 v2a = *(const float2*)(xb + 8 * G1_XROWB);
        float2 v2b = *(const float2*)(xb + 8 * G1_XROWB + 32);
        uint32_t ah0 = pack_hi(v1a), ah1 = pack_hi(v2a);
        uint32_t ah2 = pack_hi(v1b), ah3 = pack_hi(v2b);
        uint32_t al0 = pack_lo(v1a, ah0), al1 = pack_lo(v2a, ah1);
        uint32_t al2 = pack_lo(v1b, ah2), al3 = pack_lo(v2b, ah3);

        const char* kbase = bb + lane * 8 + NT0 * 256;
#pragma unroll
        for (int nt = 0; nt < 9; nt++) {
            if (nt < NT_MY) {
                uint2 bh = *(const uint2*)(kbase + nt * 256);
                uint2 bl = *(const uint2*)(kbase + NTILES * 256 + nt * 256);
                mma_bf16(acc[nt], ah0, ah1, ah2, ah3, bh.x, bh.y);
                mma_bf16(acc[nt], ah0, ah1, ah2, ah3, bl.x, bl.y);
                mma_bf16(acc[nt], al0, al1, al2, al3, bh.x, bh.y);
            }
        }
    }
    __syncthreads();   // ring dead; overlay pz

    // ---- scatter acc (+bias) into interleaved pz[row][c] ----
    // c < 65: z.x = p[c];  c >= 65: z[c-65].y = p[c]
    float* pzf = (float*)(sm + SM_PZ);
    float* sbias = (float*)(sm + SM_BIAS);
    {
        const int r1 = wr * 16 + (lane >> 2);
        const int cb = (lane & 3) * 2;
#pragma unroll
        for (int nt = 0; nt < 9; nt++) {
            if (nt < NT_MY) {
                int col0 = (NT0 + nt) * 8 + cb;
#pragma unroll
                for (int h = 0; h < 2; h++) {
                    int col = col0 + h;
                    if (col < N1) {
                        float bv = sbias[col];
                        float v0 = acc[nt][h] + bv;       // row r1
                        float v1 = acc[nt][2 + h] + bv;   // row r1+8
                        int ci = (col < L) ? col * 2 : (col - L) * 2 + 1;
                        pzf[r1 * 132 + ci] = v0;
                        pzf[(r1 + 8) * 132 + ci] = v1;
                    }
                }
            }
        }
    }
    __syncthreads();

    // ---- autocorrelation (block-local, interleaved complex) ----
    const float2* pz = (const float2*)(sm + SM_PZ);
    float* contrib = (float*)(sm + SM_CONTR);
    float* inv_r0 = (float*)(sm + SM_INVR);

    if (tid < M_CTA) {
        const float2* zr = pz + tid * 66;
        float s = 0.0f;
        for (int j = 0; j < L; j++) {
            float2 u = zr[j];
            s += u.x * u.x + u.y * u.y;
        }
        inv_r0[tid] = 1.0f / s;
    }
    __syncthreads();

    for (int t = tid; t < M_CTA * 64; t += 256) {
        int row = t >> 6;
        int lag = 1 + (t & 63);
        const float2* zr = pz + row * 66;
        float sre = 0.0f, sim = 0.0f;
        int n = L - lag;
        for (int j = 0; j < n; j++) {
            float2 u = zr[j + lag];
            float2 v = zr[j];
            sre += u.x * v.x + u.y * v.y;
            sim += u.y * v.x - u.x * v.y;
        }
        float ir = inv_r0[row];
        float cr = sre * ir;
        float ci = sim * ir;
        size_t base = (size_t)(m0 + row) * K2;
        __nv_bfloat16 crh = __float2bfloat16(cr);
        __nv_bfloat16 cih = __float2bfloat16(ci);
        g_coefh[base + (lag - 1)]     = crh;
        g_coefh[base + F + (lag - 1)] = cih;
        g_coefl[base + (lag - 1)]     = __float2bfloat16(cr - __bfloat162float(crh));
        g_coefl[base + F + (lag - 1)] = __float2bfloat16(ci - __bfloat162float(cih));
        contrib[row * 64 + (lag - 1)] = cr * g_CS[lag - 1] - ci * g_SS[lag - 1];
    }
    __syncthreads();

    if (tid < M_CTA) {
        const float* cb = contrib + tid * 64;
        float S = 0.5f * (float)D;
        for (int k = 0; k < 64; k++) S += cb[k];
        g_invS[m0 + tid] = 1.0f / S;
    }
}

// ============================================================
// Kernel 2 (HMMA): like = coef @ T (+0.5) -> log epilogue
// ============================================================
__global__ void __launch_bounds__(256)
gemm2_mma_kernel(float* __restrict__ out) {
    extern __shared__ char sm[];
    uint32_t* smB = (uint32_t*)sm;
    const int tid = threadIdx.x;
    const int w = tid >> 5;
    const int lane = tid & 31;
    const int m0 = blockIdx.x * 128;
    const int nb = blockIdx.y;

    {
        const uint4* src = (const uint4*)(g_Tfrag + (size_t)nb * SM2_U32);
        uint4* dst = (uint4*)smB;
        for (int i = tid; i < SM2_U32 / 4; i += 256) dst[i] = src[i];
    }
    __syncthreads();

    float acc[G2_NT][4];
#pragma unroll
    for (int nt = 0; nt < G2_NT; nt++)
#pragma unroll
        for (int i = 0; i < 4; i++) acc[nt][i] = 0.0f;

    const int r1 = m0 + w * 16 + (lane >> 2);
    const __nv_bfloat16* ch1 = g_coefh + (size_t)r1 * K2;
    const __nv_bfloat16* ch2 = ch1 + 8 * K2;
    const __nv_bfloat16* cl1 = g_coefl + (size_t)r1 * K2;
    const __nv_bfloat16* cl2 = cl1 + 8 * K2;
    const int kc0 = (lane & 3) * 2;

#pragma unroll
    for (int ks = 0; ks < G2_KS; ks++) {
        const int kc = ks * 16 + kc0;
        uint32_t ah0 = *(const uint32_t*)(ch1 + kc);
        uint32_t ah1 = *(const uint32_t*)(ch2 + kc);
        uint32_t ah2 = *(const uint32_t*)(ch1 + kc + 8);
        uint32_t ah3 = *(const uint32_t*)(ch2 + kc + 8);
        uint32_t al0 = *(const uint32_t*)(cl1 + kc);
        uint32_t al1 = *(const uint32_t*)(cl2 + kc);
        uint32_t al2 = *(const uint32_t*)(cl1 + kc + 8);
        uint32_t al3 = *(const uint32_t*)(cl2 + kc + 8);
#pragma unroll
        for (int nt = 0; nt < G2_NT; nt++) {
            const uint32_t* p = smB + (((nt * G2_KS + ks) * 2) * 32 + lane) * 2;
            uint2 bh = *(const uint2*)p;
            uint2 bl = *(const uint2*)(p + 64);
            mma_bf16(acc[nt], ah0, ah1, ah2, ah3, bh.x, bh.y);
            mma_bf16(acc[nt], ah0, ah1, ah2, ah3, bl.x, bl.y);
            mma_bf16(acc[nt], al0, al1, al2, al3, bh.x, bh.y);
        }
    }

    const float is0 = g_invS[r1];
    const float is1 = g_invS[r1 + 8];
    float* o0 = out + (size_t)r1 * D + nb * 128 + kc0;
    float* o1 = o0 + 8 * (size_t)D;
#pragma unroll
    for (int nt = 0; nt < G2_NT; nt++) {
        float2 u0, u1;
        u0.x = __logf(fmaf(acc[nt][0] + 0.5f, is0, 1e-5f));
        u0.y = __logf(fmaf(acc[nt][1] + 0.5f, is0, 1e-5f));
        u1.x = __logf(fmaf(acc[nt][2] + 0.5f, is1, 1e-5f));
        u1.y = __logf(fmaf(acc[nt][3] + 0.5f, is1, 1e-5f));
        *(float2*)(o0 + nt * 8) = u0;
        *(float2*)(o1 + nt * 8) = u1;
    }
}

extern "C" void kernel_launch(void* const* d_in, const int* in_sizes, int n_in,
                              void* d_out, int out_size) {
    const float* X = (const float*)d_in[0];     // batch [16,4096,1024]
    const float* Wm = (const float*)d_in[1];    // W [130,1024]
    const float* bias = (const float*)d_in[2];  // b [130]
    float* out = (float*)d_out;                 // [16,4096,512] f32

    const int rows = in_sizes[0] / DIN;         // 65536

    static bool attr_set = false;
    if (!attr_set) {
        cudaFuncSetAttribute(gemm1_mma_kernel,
                             cudaFuncAttributeMaxDynamicSharedMemorySize, SM1_BYTES);
        cudaFuncSetAttribute(gemm2_mma_kernel,
                             cudaFuncAttributeMaxDynamicSharedMemorySize, SM2_BYTES);
        attr_set = true;
    }

    table_kernel<<<F, D>>>();
    wprep_kernel<<<KSTEPS, NTILES * 32>>>(Wm);
    tprep_kernel<<<64, 256>>>();
    gemm1_mma_kernel<<<rows / M_CTA, 256, SM1_BYTES>>>(X, bias);
    gemm2_mma_kernel<<<dim3(rows / 128, 4), 256, SM2_BYTES>>>(out);
}